// round 2
// baseline (speedup 1.0000x reference)
#include <cuda_runtime.h>
#include <cuda_bf16.h>
#include <cstdint>

#define Bn   512
#define Tn   64
#define Mn   256
#define Pn   256
#define G4n  1024

// ---------------- device-global scratch (allocation-free) -------------------
__device__ float g_y1 [Bn * Tn * Mn];   // enc @ Ud^T, loop-invariant (33.5 MB)
__device__ float g_h  [Bn * Pn];
__device__ float g_s  [Bn * Pn];
__device__ float g_ct [Bn * Mn];        // last attention context
__device__ float g_x1a[Bn * Mn];        // h  @ Wd[:, :256]^T + Wd_b
__device__ float g_x1b[Bn * Mn];        // s  @ Wd[:, 256:]^T
__device__ float g_gh [Bn * G4n];       // h  @ Whh^T + bih + bhh
__device__ float g_u  [2 * Pn + 1];     // folded head: vy@Wy (512) + const

// ---------------- math helpers ---------------------------------------------
__device__ __forceinline__ float tanh_acc(float x) {
    float e = __expf(2.0f * x);
    return 1.0f - 2.0f / (e + 1.0f);
}
__device__ __forceinline__ float sigm(float x) {
    return 1.0f / (1.0f + __expf(-x));
}

__device__ __forceinline__ float block_reduce_256(float v, float* red8) {
    #pragma unroll
    for (int o = 16; o > 0; o >>= 1) v += __shfl_xor_sync(0xffffffffu, v, o);
    int w = threadIdx.x >> 5, l = threadIdx.x & 31;
    __syncthreads();                 // protect red8 across successive calls
    if (l == 0) red8[w] = v;
    __syncthreads();
    float r = red8[0];
    #pragma unroll
    for (int i = 1; i < 8; i++) r += red8[i];
    return r;
}

// ---------------- init ------------------------------------------------------
__global__ void init_state_kernel() {
    int b = blockIdx.x, m = threadIdx.x;
    g_h[b * Pn + m] = 0.0f;
    g_s[b * Pn + m] = 0.0f;
}

// ---------------- fold head: u = vy_w @ Wy_w, uc = vy_w·Wy_b + vy_b ---------
__global__ void compute_u_kernel(const float* __restrict__ vy_w,
                                 const float* __restrict__ Wy_w,
                                 const float* __restrict__ Wy_b,
                                 const float* __restrict__ vy_b) {
    int j = threadIdx.x;            // 512 threads
    float s = 0.0f;
    #pragma unroll 4
    for (int n = 0; n < Pn; n++) s += vy_w[n] * Wy_w[n * 512 + j];
    g_u[j] = s;

    // constant term: reduce vy_w[n]*Wy_b[n] over n (first 256 threads)
    __shared__ float red[16];
    float v = (j < Pn) ? vy_w[j] * Wy_b[j] : 0.0f;
    #pragma unroll
    for (int o = 16; o > 0; o >>= 1) v += __shfl_xor_sync(0xffffffffu, v, o);
    int w = j >> 5, l = j & 31;
    if (l == 0) red[w] = v;
    __syncthreads();
    if (j == 0) {
        float r = 0.0f;
        #pragma unroll
        for (int i = 0; i < 16; i++) r += red[i];
        g_u[2 * Pn] = r + vy_b[0];
    }
}

// ---------------- tiled fp32 GEMM:  C = A(rows x K) @ W^T(N x K) + b1 + b2 --
__device__ __forceinline__ void gemm_tile(const float* __restrict__ A, int lda,
                                          const float* __restrict__ W, int ldw,
                                          const float* __restrict__ b1,
                                          const float* __restrict__ b2,
                                          float* __restrict__ C, int N, int K,
                                          int bx, int by) {
    __shared__ float As[16][68];
    __shared__ float Ws[16][68];
    const int tid = threadIdx.x;
    const int r0 = bx * 64, c0 = by * 64;
    const int lr = tid >> 2;            // 0..63
    const int lk = (tid & 3) * 4;       // 0,4,8,12
    const int ty = tid >> 4, tx = tid & 15;

    float acc[4][4];
    #pragma unroll
    for (int i = 0; i < 4; i++)
        #pragma unroll
        for (int j = 0; j < 4; j++) acc[i][j] = 0.0f;

    for (int k0 = 0; k0 < K; k0 += 16) {
        float4 av = *(const float4*)&A[(r0 + lr) * lda + k0 + lk];
        As[lk + 0][lr] = av.x; As[lk + 1][lr] = av.y;
        As[lk + 2][lr] = av.z; As[lk + 3][lr] = av.w;
        float4 wv = *(const float4*)&W[(c0 + lr) * ldw + k0 + lk];
        Ws[lk + 0][lr] = wv.x; Ws[lk + 1][lr] = wv.y;
        Ws[lk + 2][lr] = wv.z; Ws[lk + 3][lr] = wv.w;
        __syncthreads();
        #pragma unroll
        for (int k = 0; k < 16; k++) {
            float4 a = *(const float4*)&As[k][ty * 4];
            float4 w = *(const float4*)&Ws[k][tx * 4];
            const float ar[4] = {a.x, a.y, a.z, a.w};
            const float wr[4] = {w.x, w.y, w.z, w.w};
            #pragma unroll
            for (int i = 0; i < 4; i++)
                #pragma unroll
                for (int j = 0; j < 4; j++)
                    acc[i][j] += ar[i] * wr[j];
        }
        __syncthreads();
    }

    #pragma unroll
    for (int i = 0; i < 4; i++) {
        int row = r0 + ty * 4 + i;
        #pragma unroll
        for (int j = 0; j < 4; j++) {
            int col = c0 + tx * 4 + j;
            float bias = 0.0f;
            if (b1) bias += b1[col];
            if (b2) bias += b2[col];
            C[row * N + col] = acc[i][j] + bias;
        }
    }
}

// y1[b*t, n] = enc[b*t, :] · Ud_w[n, :]
__global__ void y1_gemm_kernel(const float* __restrict__ enc,
                               const float* __restrict__ Ud_w) {
    gemm_tile(enc, Mn, Ud_w, Mn, nullptr, nullptr, g_y1, Mn, Mn,
              blockIdx.x, blockIdx.y);
}

// per-step GEMMs: z=0 -> x1a, z=1 -> x1b, z=2 -> ghh
__global__ void step_gemm_kernel(const float* __restrict__ Wd_w,
                                 const float* __restrict__ Wd_b,
                                 const float* __restrict__ Whh,
                                 const float* __restrict__ bih,
                                 const float* __restrict__ bhh,
                                 int zbase) {
    int z = blockIdx.z + zbase;
    if (z == 0) {
        if (blockIdx.y >= 4) return;
        gemm_tile(g_h, Pn, Wd_w, 2 * Pn, Wd_b, nullptr, g_x1a, Mn, Pn,
                  blockIdx.x, blockIdx.y);
    } else if (z == 1) {
        if (blockIdx.y >= 4) return;
        gemm_tile(g_s, Pn, Wd_w + Pn, 2 * Pn, nullptr, nullptr, g_x1b, Mn, Pn,
                  blockIdx.x, blockIdx.y);
    } else {
        gemm_tile(g_h, Pn, Whh, Pn, bih, bhh, g_gh, G4n, Pn,
                  blockIdx.x, blockIdx.y);
    }
}

// ---------------- fused attention + LSTM step (one CTA per batch row) -------
__global__ void attn_step_kernel(const float* __restrict__ enc,
                                 const float* __restrict__ y,
                                 const float* __restrict__ vd_w,
                                 const float* __restrict__ wt_w,
                                 const float* __restrict__ wt_b,
                                 const float* __restrict__ Wih,
                                 int t_step) {
    const int b = blockIdx.x;
    const int tid = threadIdx.x;          // 256 threads, 8 warps
    const int w = tid >> 5, l = tid & 31;

    __shared__ float x1s[Mn];
    __shared__ float vs[Mn];
    __shared__ float ls[Tn];              // logits then beta
    __shared__ float red8[8];
    __shared__ float s_ytil;

    // phase 1: x1 = x1a + x1b (bias already folded into x1a), cache v
    x1s[tid] = g_x1a[b * Mn + tid] + g_x1b[b * Mn + tid];
    vs[tid]  = vd_w[tid];
    __syncthreads();

    // phase 2: logits l[t] = sum_m tanh(x1[m] + y1[b,t,m]) * v[m]
    #pragma unroll
    for (int idx = 0; idx < 8; idx++) {
        int t = w * 8 + idx;
        const float* y1row = &g_y1[(b * Tn + t) * Mn];
        float sum = 0.0f;
        #pragma unroll
        for (int j = 0; j < 8; j++) {
            int m = l + 32 * j;
            sum += tanh_acc(x1s[m] + y1row[m]) * vs[m];
        }
        #pragma unroll
        for (int o = 16; o > 0; o >>= 1) sum += __shfl_xor_sync(0xffffffffu, sum, o);
        if (l == 0) ls[t] = sum;
    }
    __syncthreads();

    // phase 3: softmax over T=64 (warp 0, 2 per lane)
    if (w == 0) {
        float a = ls[l], c = ls[l + 32];
        float mx = fmaxf(a, c);
        #pragma unroll
        for (int o = 16; o > 0; o >>= 1) mx = fmaxf(mx, __shfl_xor_sync(0xffffffffu, mx, o));
        float e0 = __expf(a - mx), e1 = __expf(c - mx);
        float ts = e0 + e1;
        #pragma unroll
        for (int o = 16; o > 0; o >>= 1) ts += __shfl_xor_sync(0xffffffffu, ts, o);
        ls[l]      = e0 / ts;
        ls[l + 32] = e1 / ts;
    }
    __syncthreads();

    // phase 4: context c_t[m] = sum_t beta[t] * enc[b,t,m]
    const int m = tid;
    float acc = 0.0f;
    const float* encb = &enc[b * Tn * Mn];
    #pragma unroll 4
    for (int t = 0; t < Tn; t++) acc += ls[t] * encb[t * Mn + m];
    g_ct[b * Mn + m] = acc;

    // phase 5: y_til = c_t · wt_w[:256] + y[b,t]*wt_w[256] + wt_b
    float tot = block_reduce_256(acc * wt_w[m], red8);
    if (tid == 0)
        s_ytil = tot + y[b * Tn + t_step] * wt_w[Mn] + wt_b[0];
    __syncthreads();
    const float ytil = s_ytil;

    // phase 6: LSTM cell (gate order i,f,g,o; bih+bhh folded into g_gh)
    const float* gh = &g_gh[b * G4n];
    float ig = gh[tid]           + ytil * Wih[tid];
    float fg = gh[tid + Pn]      + ytil * Wih[tid + Pn];
    float gg = gh[tid + 2 * Pn]  + ytil * Wih[tid + 2 * Pn];
    float og = gh[tid + 3 * Pn]  + ytil * Wih[tid + 3 * Pn];
    float cn = sigm(fg) * g_s[b * Pn + tid] + sigm(ig) * tanh_acc(gg);
    float hn = sigm(og) * tanh_acc(cn);
    g_s[b * Pn + tid] = cn;
    g_h[b * Pn + tid] = hn;
}

// ---------------- y_Tp1 head (warp per batch row) ---------------------------
__global__ void head1_kernel(float* __restrict__ out) {
    int w = threadIdx.x >> 5, l = threadIdx.x & 31;
    int b = blockIdx.x * 8 + w;
    float sum = 0.0f;
    #pragma unroll
    for (int j = l; j < Pn; j += 32)
        sum += g_h[b * Pn + j] * g_u[j] + g_ct[b * Mn + j] * g_u[Pn + j];
    #pragma unroll
    for (int o = 16; o > 0; o >>= 1) sum += __shfl_xor_sync(0xffffffffu, sum, o);
    if (l == 0) out[b] = sum + g_u[2 * Pn];
}

// ---------------- extra step e (0 or 1): y_til, LSTM, head ------------------
__global__ void extra_step_kernel(const float* __restrict__ tar,
                                  const int* __restrict__ trainp,
                                  const float* __restrict__ wt_w,
                                  const float* __restrict__ wt_b,
                                  const float* __restrict__ Wih,
                                  float* __restrict__ out, int e) {
    const int b = blockIdx.x, tid = threadIdx.x;
    __shared__ float red8[8];
    __shared__ float s_ytil;

    const float ct = g_ct[b * Mn + tid];
    float dct = block_reduce_256(ct * wt_w[tid], red8);
    if (tid == 0) {
        int train = (trainp[0] != 0);    // nonzero for int 1 or float 1.0 bits
        float inp = train ? tar[b * 2 + e] : out[e * Bn + b];
        s_ytil = dct + inp * wt_w[Mn] + wt_b[0];
    }
    __syncthreads();
    const float ytil = s_ytil;

    const float* gh = &g_gh[b * G4n];
    float ig = gh[tid]          + ytil * Wih[tid];
    float fg = gh[tid + Pn]     + ytil * Wih[tid + Pn];
    float gg = gh[tid + 2 * Pn] + ytil * Wih[tid + 2 * Pn];
    float og = gh[tid + 3 * Pn] + ytil * Wih[tid + 3 * Pn];
    float cn = sigm(fg) * g_s[b * Pn + tid] + sigm(ig) * tanh_acc(gg);
    float hn = sigm(og) * tanh_acc(cn);
    g_s[b * Pn + tid] = cn;
    g_h[b * Pn + tid] = hn;

    float tot = block_reduce_256(hn * g_u[tid] + ct * g_u[Pn + tid], red8);
    if (tid == 0) out[(e + 1) * Bn + b] = tot + g_u[2 * Pn];
}

// ---------------- launcher --------------------------------------------------
extern "C" void kernel_launch(void* const* d_in, const int* in_sizes, int n_in,
                              void* d_out, int out_size) {
    const float* enc   = (const float*)d_in[0];
    const float* y     = (const float*)d_in[1];
    const float* tar   = (const float*)d_in[2];
    const int*   train = (const int*)  d_in[3];
    const float* Wd_w  = (const float*)d_in[4];
    const float* Wd_b  = (const float*)d_in[5];
    const float* Ud_w  = (const float*)d_in[6];
    const float* vd_w  = (const float*)d_in[7];
    const float* wt_w  = (const float*)d_in[8];
    const float* wt_b  = (const float*)d_in[9];
    const float* Wy_w  = (const float*)d_in[10];
    const float* Wy_b  = (const float*)d_in[11];
    const float* vy_w  = (const float*)d_in[12];
    const float* vy_b  = (const float*)d_in[13];
    const float* Wih   = (const float*)d_in[14];
    const float* Whh   = (const float*)d_in[15];
    const float* bih   = (const float*)d_in[16];
    const float* bhh   = (const float*)d_in[17];
    float* out = (float*)d_out;

    init_state_kernel<<<Bn, Pn>>>();
    compute_u_kernel<<<1, 512>>>(vy_w, Wy_w, Wy_b, vy_b);
    y1_gemm_kernel<<<dim3(Bn * Tn / 64, Mn / 64), 256>>>(enc, Ud_w);

    for (int t = 0; t < Tn; t++) {
        step_gemm_kernel<<<dim3(8, 16, 3), 256>>>(Wd_w, Wd_b, Whh, bih, bhh, 0);
        attn_step_kernel<<<Bn, 256>>>(enc, y, vd_w, wt_w, wt_b, Wih, t);
    }

    head1_kernel<<<Bn / 8, 256>>>(out);

    for (int e = 0; e < 2; e++) {
        step_gemm_kernel<<<dim3(8, 16, 1), 256>>>(Wd_w, Wd_b, Whh, bih, bhh, 2);
        extra_step_kernel<<<Bn, 256>>>(tar, train, wt_w, wt_b, Wih, out, e);
    }
}

// round 5
// speedup vs baseline: 1.0535x; 1.0535x over previous
#include <cuda_runtime.h>
#include <cuda_bf16.h>
#include <cstdint>

#define Bn   512
#define Tn   64
#define Mn   256
#define Pn   256
#define G4n  1024

// ---------------- device-global scratch (allocation-free) -------------------
__device__ __align__(256) float g_y1 [Bn * Tn * Mn]; // enc @ Ud^T (33.5 MB)
__device__ __align__(256) float g_hs [Bn * 2 * Pn];  // [h | s] per row, lda=512
__device__ __align__(256) float g_ct [Bn * Mn];      // attention context
__device__ __align__(256) float g_x1p0[Bn * Mn];     // split-K partials of x1
__device__ __align__(256) float g_x1p1[Bn * Mn];
__device__ __align__(256) float g_ghp0[Bn * G4n];    // split-K partials of gh
__device__ __align__(256) float g_ghp1[Bn * G4n];
__device__ __align__(256) float g_u  [2 * Pn + 1];   // folded head vector

// ---------------- math helpers ---------------------------------------------
__device__ __forceinline__ float tanh_acc(float x) {
    float e = __expf(2.0f * x);
    return 1.0f - __fdividef(2.0f, e + 1.0f);
}
__device__ __forceinline__ float sigm(float x) {
    return __fdividef(1.0f, 1.0f + __expf(-x));
}

__device__ __forceinline__ float block_reduce_256(float v, float* red8) {
    #pragma unroll
    for (int o = 16; o > 0; o >>= 1) v += __shfl_xor_sync(0xffffffffu, v, o);
    int w = threadIdx.x >> 5, l = threadIdx.x & 31;
    __syncthreads();                 // protect red8 across successive calls
    if (l == 0) red8[w] = v;
    __syncthreads();
    float r = red8[0];
    #pragma unroll
    for (int i = 1; i < 8; i++) r += red8[i];
    return r;
}

// ---------------- init ------------------------------------------------------
__global__ void init_state_kernel() {
    g_hs[blockIdx.x * 512 + threadIdx.x] = 0.0f;
}

// ---------------- fold head: u = vy_w @ Wy_w, uc = vy_w·Wy_b + vy_b ---------
__global__ void compute_u_kernel(const float* __restrict__ vy_w,
                                 const float* __restrict__ Wy_w,
                                 const float* __restrict__ Wy_b,
                                 const float* __restrict__ vy_b) {
    int j = threadIdx.x;            // 512 threads
    float s = 0.0f;
    #pragma unroll 4
    for (int n = 0; n < Pn; n++) s += vy_w[n] * Wy_w[n * 512 + j];
    g_u[j] = s;

    __shared__ float red[16];
    float v = (j < Pn) ? vy_w[j] * Wy_b[j] : 0.0f;
    #pragma unroll
    for (int o = 16; o > 0; o >>= 1) v += __shfl_xor_sync(0xffffffffu, v, o);
    int w = j >> 5, l = j & 31;
    if (l == 0) red[w] = v;
    __syncthreads();
    if (j == 0) {
        float r = 0.0f;
        #pragma unroll
        for (int i = 0; i < 16; i++) r += red[i];
        g_u[2 * Pn] = r + vy_b[0];
    }
}

// ---------------- 64x64 fp32 GEMM tile, 64 threads, 8x8 regs, dbl-buffered --
// C[r0+i, c0+j] (+= bias) = sum_{k in [k0,k0+klen)} A[row, k] * W[col, k]
__device__ __forceinline__ void gemm_tile64(
    const float* __restrict__ A, int lda,
    const float* __restrict__ W, int ldw,
    float* __restrict__ C, int ldc,
    const float* __restrict__ b1, const float* __restrict__ b2,
    int r0, int c0, int k0, int klen)
{
    __shared__ __align__(16) float As[2][16][68];
    __shared__ __align__(16) float Ws[2][16][68];
    const int t  = threadIdx.x;       // 0..63
    const int ty = t >> 3, tx = t & 7;

    float acc[8][8];
    #pragma unroll
    for (int i = 0; i < 8; i++)
        #pragma unroll
        for (int j = 0; j < 8; j++) acc[i][j] = 0.0f;

    const float* Arow = A + (size_t)(r0 + t) * lda + k0;
    const float* Wrow = W + (size_t)(c0 + t) * ldw + k0;

    float4 ar[4], wr[4];
    #pragma unroll
    for (int q = 0; q < 4; q++) {
        ar[q] = *(const float4*)(Arow + q * 4);
        wr[q] = *(const float4*)(Wrow + q * 4);
    }
    #pragma unroll
    for (int q = 0; q < 4; q++) {
        As[0][q*4+0][t] = ar[q].x; As[0][q*4+1][t] = ar[q].y;
        As[0][q*4+2][t] = ar[q].z; As[0][q*4+3][t] = ar[q].w;
        Ws[0][q*4+0][t] = wr[q].x; Ws[0][q*4+1][t] = wr[q].y;
        Ws[0][q*4+2][t] = wr[q].z; Ws[0][q*4+3][t] = wr[q].w;
    }
    __syncthreads();

    const int nc = klen >> 4;
    for (int c = 0; c < nc; c++) {
        const int cur = c & 1;
        if (c + 1 < nc) {
            const float* Ap = Arow + (c + 1) * 16;
            const float* Wp = Wrow + (c + 1) * 16;
            #pragma unroll
            for (int q = 0; q < 4; q++) {
                ar[q] = *(const float4*)(Ap + q * 4);
                wr[q] = *(const float4*)(Wp + q * 4);
            }
        }
        #pragma unroll
        for (int k = 0; k < 16; k++) {
            float a0[8], w0[8];
            *(float4*)&a0[0] = *(const float4*)&As[cur][k][ty * 8];
            *(float4*)&a0[4] = *(const float4*)&As[cur][k][ty * 8 + 4];
            *(float4*)&w0[0] = *(const float4*)&Ws[cur][k][tx * 8];
            *(float4*)&w0[4] = *(const float4*)&Ws[cur][k][tx * 8 + 4];
            #pragma unroll
            for (int i = 0; i < 8; i++)
                #pragma unroll
                for (int j = 0; j < 8; j++)
                    acc[i][j] += a0[i] * w0[j];
        }
        if (c + 1 < nc) {
            const int nxt = cur ^ 1;
            #pragma unroll
            for (int q = 0; q < 4; q++) {
                As[nxt][q*4+0][t] = ar[q].x; As[nxt][q*4+1][t] = ar[q].y;
                As[nxt][q*4+2][t] = ar[q].z; As[nxt][q*4+3][t] = ar[q].w;
                Ws[nxt][q*4+0][t] = wr[q].x; Ws[nxt][q*4+1][t] = wr[q].y;
                Ws[nxt][q*4+2][t] = wr[q].z; Ws[nxt][q*4+3][t] = wr[q].w;
            }
            __syncthreads();
        }
    }

    #pragma unroll
    for (int i = 0; i < 8; i++) {
        const int row = r0 + ty * 8 + i;
        #pragma unroll
        for (int j = 0; j < 8; j += 4) {
            const int col = c0 + tx * 8 + j;
            float4 v = make_float4(acc[i][j], acc[i][j+1], acc[i][j+2], acc[i][j+3]);
            if (b1) { v.x += b1[col]; v.y += b1[col+1]; v.z += b1[col+2]; v.w += b1[col+3]; }
            if (b2) { v.x += b2[col]; v.y += b2[col+1]; v.z += b2[col+2]; v.w += b2[col+3]; }
            *(float4*)&C[(size_t)row * ldc + col] = v;
        }
    }
}

// y1[b*t, n] = enc[b*t, :] · Ud_w[n, :]
__global__ void __launch_bounds__(64) y1_gemm_kernel(const float* __restrict__ enc,
                                                     const float* __restrict__ Ud_w) {
    gemm_tile64(enc, Mn, Ud_w, Mn, g_y1, Mn, nullptr, nullptr,
                blockIdx.x * 64, blockIdx.y * 64, 0, Mn);
}

// per-step GEMMs, split-K:
//   z=0: x1 part0 = hs[:, 0:256] @ Wd[:, 0:256]^T + Wd_b
//   z=1: x1 part1 = hs[:,256:512] @ Wd[:,256:512]^T
//   z=2: gh part0 = h @ Whh[:, 0:128]^T + bih + bhh
//   z=3: gh part1 = h @ Whh[:,128:256]^T
__global__ void __launch_bounds__(64) step_gemm_kernel(
        const float* __restrict__ Wd_w, const float* __restrict__ Wd_b,
        const float* __restrict__ Whh,  const float* __restrict__ bih,
        const float* __restrict__ bhh,  int zbase) {
    const int z = blockIdx.z + zbase;
    const int r0 = blockIdx.x * 64, c0 = blockIdx.y * 64;
    if (z == 0) {
        if (blockIdx.y >= 4) return;
        gemm_tile64(g_hs, 512, Wd_w, 512, g_x1p0, Mn, Wd_b, nullptr, r0, c0, 0, 256);
    } else if (z == 1) {
        if (blockIdx.y >= 4) return;
        gemm_tile64(g_hs, 512, Wd_w, 512, g_x1p1, Mn, nullptr, nullptr, r0, c0, 256, 256);
    } else if (z == 2) {
        gemm_tile64(g_hs, 512, Whh, 256, g_ghp0, G4n, bih, bhh, r0, c0, 0, 128);
    } else {
        gemm_tile64(g_hs, 512, Whh, 256, g_ghp1, G4n, nullptr, nullptr, r0, c0, 128, 128);
    }
}

// ---------------- fused attention + LSTM step (one CTA per batch row) -------
__global__ void __launch_bounds__(256) attn_step_kernel(
        const float* __restrict__ enc, const float* __restrict__ y,
        const float* __restrict__ vd_w, const float* __restrict__ wt_w,
        const float* __restrict__ wt_b, const float* __restrict__ Wih,
        int t_step) {
    const int b = blockIdx.x;
    const int tid = threadIdx.x;          // 256 threads, 8 warps
    const int w = tid >> 5, l = tid & 31;

    __shared__ float x1s[Mn];
    __shared__ float vs[Mn];
    __shared__ float ls[Tn];
    __shared__ float red8[8];
    __shared__ float s_ytil;

    // phase 1: x1 = split-K partial sum (bias folded into part0)
    x1s[tid] = g_x1p0[b * Mn + tid] + g_x1p1[b * Mn + tid];
    vs[tid]  = vd_w[tid];
    __syncthreads();

    // phase 2: logits l[t] = sum_m tanh(x1[m] + y1[b,t,m]) * v[m]
    #pragma unroll
    for (int idx = 0; idx < 8; idx++) {
        int t = w * 8 + idx;
        const float* y1row = &g_y1[((size_t)b * Tn + t) * Mn];
        float sum = 0.0f;
        #pragma unroll
        for (int j = 0; j < 8; j++) {
            int m = l + 32 * j;
            sum += tanh_acc(x1s[m] + y1row[m]) * vs[m];
        }
        #pragma unroll
        for (int o = 16; o > 0; o >>= 1) sum += __shfl_xor_sync(0xffffffffu, sum, o);
        if (l == 0) ls[t] = sum;
    }
    __syncthreads();

    // phase 3: softmax over T=64 (warp 0)
    if (w == 0) {
        float a = ls[l], c = ls[l + 32];
        float mx = fmaxf(a, c);
        #pragma unroll
        for (int o = 16; o > 0; o >>= 1) mx = fmaxf(mx, __shfl_xor_sync(0xffffffffu, mx, o));
        float e0 = __expf(a - mx), e1 = __expf(c - mx);
        float ts = e0 + e1;
        #pragma unroll
        for (int o = 16; o > 0; o >>= 1) ts += __shfl_xor_sync(0xffffffffu, ts, o);
        float inv = __fdividef(1.0f, ts);
        ls[l]      = e0 * inv;
        ls[l + 32] = e1 * inv;
    }
    __syncthreads();

    // phase 4: context c_t[m] = sum_t beta[t] * enc[b,t,m]
    const int m = tid;
    float acc = 0.0f;
    const float* encb = &enc[(size_t)b * Tn * Mn];
    #pragma unroll 8
    for (int t = 0; t < Tn; t++) acc += ls[t] * encb[t * Mn + m];
    g_ct[b * Mn + m] = acc;

    // phase 5: y_til = c_t · wt_w[:256] + y[b,t]*wt_w[256] + wt_b
    float tot = block_reduce_256(acc * wt_w[m], red8);
    if (tid == 0)
        s_ytil = tot + y[b * Tn + t_step] * wt_w[Mn] + wt_b[0];
    __syncthreads();
    const float ytil = s_ytil;

    // phase 6: LSTM cell (gate order i,f,g,o; biases folded into gh part0)
    const float* gh0 = &g_ghp0[(size_t)b * G4n];
    const float* gh1 = &g_ghp1[(size_t)b * G4n];
    float ig = gh0[tid]          + gh1[tid]          + ytil * Wih[tid];
    float fg = gh0[tid + Pn]     + gh1[tid + Pn]     + ytil * Wih[tid + Pn];
    float gg = gh0[tid + 2*Pn]   + gh1[tid + 2*Pn]   + ytil * Wih[tid + 2*Pn];
    float og = gh0[tid + 3*Pn]   + gh1[tid + 3*Pn]   + ytil * Wih[tid + 3*Pn];
    float so = g_hs[b * 512 + 256 + tid];
    float cn = sigm(fg) * so + sigm(ig) * tanh_acc(gg);
    float hn = sigm(og) * tanh_acc(cn);
    g_hs[b * 512 + 256 + tid] = cn;
    g_hs[b * 512 + tid]       = hn;
}

// ---------------- y_Tp1 head (warp per batch row) ---------------------------
__global__ void __launch_bounds__(256) head1_kernel(float* __restrict__ out) {
    int w = threadIdx.x >> 5, l = threadIdx.x & 31;
    int b = blockIdx.x * 8 + w;
    float sum = 0.0f;
    #pragma unroll
    for (int j = l; j < Pn; j += 32)
        sum += g_hs[b * 512 + j] * g_u[j] + g_ct[b * Mn + j] * g_u[Pn + j];
    #pragma unroll
    for (int o = 16; o > 0; o >>= 1) sum += __shfl_xor_sync(0xffffffffu, sum, o);
    if (l == 0) out[b] = sum + g_u[2 * Pn];
}

// ---------------- extra step e (0 or 1): y_til, LSTM, head ------------------
__global__ void __launch_bounds__(256) extra_step_kernel(
        const float* __restrict__ tar, const int* __restrict__ trainp,
        const float* __restrict__ wt_w, const float* __restrict__ wt_b,
        const float* __restrict__ Wih, float* __restrict__ out, int e) {
    const int b = blockIdx.x, tid = threadIdx.x;
    __shared__ float red8[8];
    __shared__ float s_ytil;

    const float ct = g_ct[b * Mn + tid];
    float dct = block_reduce_256(ct * wt_w[tid], red8);
    if (tid == 0) {
        int train = (trainp[0] != 0);
        float inp = train ? tar[b * 2 + e] : out[e * Bn + b];
        s_ytil = dct + inp * wt_w[Mn] + wt_b[0];
    }
    __syncthreads();
    const float ytil = s_ytil;

    const float* gh0 = &g_ghp0[(size_t)b * G4n];
    const float* gh1 = &g_ghp1[(size_t)b * G4n];
    float ig = gh0[tid]        + gh1[tid]        + ytil * Wih[tid];
    float fg = gh0[tid + Pn]   + gh1[tid + Pn]   + ytil * Wih[tid + Pn];
    float gg = gh0[tid + 2*Pn] + gh1[tid + 2*Pn] + ytil * Wih[tid + 2*Pn];
    float og = gh0[tid + 3*Pn] + gh1[tid + 3*Pn] + ytil * Wih[tid + 3*Pn];
    float so = g_hs[b * 512 + 256 + tid];
    float cn = sigm(fg) * so + sigm(ig) * tanh_acc(gg);
    float hn = sigm(og) * tanh_acc(cn);
    g_hs[b * 512 + 256 + tid] = cn;
    g_hs[b * 512 + tid]       = hn;

    float tot = block_reduce_256(hn * g_u[tid] + ct * g_u[Pn + tid], red8);
    if (tid == 0) out[(e + 1) * Bn + b] = tot + g_u[2 * Pn];
}

// ---------------- launcher --------------------------------------------------
extern "C" void kernel_launch(void* const* d_in, const int* in_sizes, int n_in,
                              void* d_out, int out_size) {
    const float* enc   = (const float*)d_in[0];
    const float* y     = (const float*)d_in[1];
    const float* tar   = (const float*)d_in[2];
    const int*   train = (const int*)  d_in[3];
    const float* Wd_w  = (const float*)d_in[4];
    const float* Wd_b  = (const float*)d_in[5];
    const float* Ud_w  = (const float*)d_in[6];
    const float* vd_w  = (const float*)d_in[7];
    const float* wt_w  = (const float*)d_in[8];
    const float* wt_b  = (const float*)d_in[9];
    const float* Wy_w  = (const float*)d_in[10];
    const float* Wy_b  = (const float*)d_in[11];
    const float* vy_w  = (const float*)d_in[12];
    const float* vy_b  = (const float*)d_in[13];
    const float* Wih   = (const float*)d_in[14];
    const float* Whh   = (const float*)d_in[15];
    const float* bih   = (const float*)d_in[16];
    const float* bhh   = (const float*)d_in[17];
    float* out = (float*)d_out;

    init_state_kernel<<<Bn, 512>>>();
    compute_u_kernel<<<1, 512>>>(vy_w, Wy_w, Wy_b, vy_b);
    y1_gemm_kernel<<<dim3(Bn * Tn / 64, Mn / 64), 64>>>(enc, Ud_w);

    for (int t = 0; t < Tn; t++) {
        step_gemm_kernel<<<dim3(8, 16, 4), 64>>>(Wd_w, Wd_b, Whh, bih, bhh, 0);
        attn_step_kernel<<<Bn, 256>>>(enc, y, vd_w, wt_w, wt_b, Wih, t);
    }

    head1_kernel<<<Bn / 8, 256>>>(out);

    for (int e = 0; e < 2; e++) {
        step_gemm_kernel<<<dim3(8, 16, 2), 64>>>(Wd_w, Wd_b, Whh, bih, bhh, 2);
        extra_step_kernel<<<Bn, 256>>>(tar, train, wt_w, wt_b, Wih, out, e);
    }
}

// round 6
// speedup vs baseline: 2.2949x; 2.1783x over previous
#include <cuda_runtime.h>
#include <cuda_bf16.h>
#include <cstdint>

#define Bn   512
#define Tn   64
#define Mn   256
#define Pn   256
#define G4n  1024
#define SAS  72           // smem k-stride (bf16 elems): 144B -> conflict-free ldmatrix

// ---------------- device-global scratch (allocation-free) -------------------
__device__ __align__(256) float g_y1 [Bn * Tn * Mn]; // enc @ Ud^T (33.5 MB)
__device__ __align__(256) float g_hs [Bn * 2 * Pn];  // [h | s], lda=512 (fp32 truth)
__device__ __align__(256) float g_ct [Bn * Mn];
__device__ __align__(256) float g_x1 [Bn * Mn];      // Wd GEMM out (+Wd_b)
__device__ __align__(256) float g_gh [Bn * G4n];     // Whh GEMM out (+bih+bhh)
__device__ __align__(256) float g_u  [2 * Pn + 1];

// bf16 hi/lo split operands for tensor-core GEMMs
__device__ __align__(256) __nv_bfloat16 g_hs_hi [Bn * 2 * Pn];
__device__ __align__(256) __nv_bfloat16 g_hs_lo [Bn * 2 * Pn];
__device__ __align__(256) __nv_bfloat16 g_Wd_hi [Mn * 2 * Pn];
__device__ __align__(256) __nv_bfloat16 g_Wd_lo [Mn * 2 * Pn];
__device__ __align__(256) __nv_bfloat16 g_Whh_hi[G4n * Pn];
__device__ __align__(256) __nv_bfloat16 g_Whh_lo[G4n * Pn];

// ---------------- math helpers ---------------------------------------------
__device__ __forceinline__ float tanh_acc(float x) {
    float e = __expf(2.0f * x);
    return 1.0f - __fdividef(2.0f, e + 1.0f);
}
__device__ __forceinline__ float sigm(float x) {
    return __fdividef(1.0f, 1.0f + __expf(-x));
}
__device__ __forceinline__ float block_reduce_256(float v, float* red8) {
    #pragma unroll
    for (int o = 16; o > 0; o >>= 1) v += __shfl_xor_sync(0xffffffffu, v, o);
    int w = threadIdx.x >> 5, l = threadIdx.x & 31;
    __syncthreads();
    if (l == 0) red8[w] = v;
    __syncthreads();
    float r = red8[0];
    #pragma unroll
    for (int i = 1; i < 8; i++) r += red8[i];
    return r;
}
__device__ __forceinline__ void split_store(float v, __nv_bfloat16* hi,
                                            __nv_bfloat16* lo) {
    __nv_bfloat16 h = __float2bfloat16(v);
    *hi = h;
    *lo = __float2bfloat16(v - __bfloat162float(h));
}

// ---------------- mma / ldmatrix primitives ---------------------------------
__device__ __forceinline__ void ldm4(uint32_t* r, uint32_t addr) {
    asm volatile("ldmatrix.sync.aligned.m8n8.x4.shared.b16 {%0,%1,%2,%3}, [%4];"
        : "=r"(r[0]), "=r"(r[1]), "=r"(r[2]), "=r"(r[3]) : "r"(addr));
}
__device__ __forceinline__ void mma_bf16(float* d, const uint32_t* a,
                                         uint32_t b0, uint32_t b1) {
    asm volatile(
        "mma.sync.aligned.m16n8k16.row.col.f32.bf16.bf16.f32 "
        "{%0,%1,%2,%3}, {%4,%5,%6,%7}, {%8,%9}, {%0,%1,%2,%3};"
        : "+f"(d[0]), "+f"(d[1]), "+f"(d[2]), "+f"(d[3])
        : "r"(a[0]), "r"(a[1]), "r"(a[2]), "r"(a[3]), "r"(b0), "r"(b1));
}

// ---------------- init / weight conversion ----------------------------------
__global__ void init_state_kernel() {
    int i = blockIdx.x * 512 + threadIdx.x;
    g_hs[i] = 0.0f;
    g_hs_hi[i] = __float2bfloat16(0.0f);
    g_hs_lo[i] = __float2bfloat16(0.0f);
}
__global__ void conv_weights_kernel(const float* __restrict__ Wd,
                                    const float* __restrict__ Whh) {
    int i = blockIdx.x * 256 + threadIdx.x;
    if (i < Mn * 2 * Pn) split_store(Wd[i], &g_Wd_hi[i], &g_Wd_lo[i]);
    if (i < G4n * Pn)    split_store(Whh[i], &g_Whh_hi[i], &g_Whh_lo[i]);
}

// ---------------- fold head: u = vy_w @ Wy_w, uc = vy_w·Wy_b + vy_b ---------
__global__ void compute_u_kernel(const float* __restrict__ vy_w,
                                 const float* __restrict__ Wy_w,
                                 const float* __restrict__ Wy_b,
                                 const float* __restrict__ vy_b) {
    int j = threadIdx.x;            // 512 threads
    float s = 0.0f;
    #pragma unroll 4
    for (int n = 0; n < Pn; n++) s += vy_w[n] * Wy_w[n * 512 + j];
    g_u[j] = s;
    __shared__ float red[16];
    float v = (j < Pn) ? vy_w[j] * Wy_b[j] : 0.0f;
    #pragma unroll
    for (int o = 16; o > 0; o >>= 1) v += __shfl_xor_sync(0xffffffffu, v, o);
    int w = j >> 5, l = j & 31;
    if (l == 0) red[w] = v;
    __syncthreads();
    if (j == 0) {
        float r = 0.0f;
        #pragma unroll
        for (int i = 0; i < 16; i++) r += red[i];
        g_u[2 * Pn] = r + vy_b[0];
    }
}

// ---------------- tensor-core step GEMM --------------------------------------
// Tile 64x64, 256 threads (8 warps, 4x2 warp grid, 16x32 per warp).
// ytile<4 : x1 = hs(512x512) @ Wd^T (N=256, K=512) + Wd_b
// ytile>=4: gh = h (512x256) @ Whh^T (N=1024,K=256) + bih + bhh
__global__ void __launch_bounds__(256) step_gemm_mma(
        const float* __restrict__ Wd_b, const float* __restrict__ bih,
        const float* __restrict__ bhh, int ghonly) {
    __shared__ __align__(16) __nv_bfloat16 sA[2][64][SAS];
    __shared__ __align__(16) __nv_bfloat16 sB[2][64][SAS];

    const int tid  = threadIdx.x;
    const int wid  = tid >> 5, lane = tid & 31;
    const int wr   = wid & 3, wc = wid >> 2;        // warp row/col in tile
    const int ytile = blockIdx.y + (ghonly ? 4 : 0);
    const int r0 = blockIdx.x * 64;
    const bool isX1 = (ytile < 4);
    const int c0   = isX1 ? ytile * 64 : (ytile - 4) * 64;
    const int K    = isX1 ? 512 : 256;
    const int ldb  = isX1 ? 512 : 256;
    const int ldc  = isX1 ? Mn  : G4n;
    const __nv_bfloat16* Bh = isX1 ? g_Wd_hi : g_Whh_hi;
    const __nv_bfloat16* Bl = isX1 ? g_Wd_lo : g_Whh_lo;
    float* C = isX1 ? g_x1 : g_gh;

    float acc[4][4];
    #pragma unroll
    for (int n = 0; n < 4; n++)
        #pragma unroll
        for (int i = 0; i < 4; i++) acc[n][i] = 0.0f;

    // ldmatrix lane->address mapping
    const int grp = lane >> 3, lr = lane & 7;
    const uint32_t sA0 = (uint32_t)__cvta_generic_to_shared(&sA[0][0][0]);
    const uint32_t sB0 = (uint32_t)__cvta_generic_to_shared(&sB[0][0][0]);
    const uint32_t LOOFF = 64 * SAS * 2;            // bytes: hi plane -> lo plane
    // A frag: rows (grp&1)*8+lr, k-col (grp>>1)*8
    const uint32_t aAddr = sA0 +
        ((uint32_t)(wr * 16 + ((grp & 1) << 3) + lr) * SAS + ((grp >> 1) << 3)) * 2;
    // B frag: n-rows (grp>>1)*8+lr, k-col (grp&1)*8 ; second pair +16 n-rows
    const uint32_t bAddr = sB0 +
        ((uint32_t)(wc * 32 + ((grp >> 1) << 3) + lr) * SAS + ((grp & 1) << 3)) * 2;
    const uint32_t bAddrP1 = bAddr + 16 * SAS * 2;

    const int nchunks = K >> 6;
    for (int kc = 0; kc < nchunks; kc++) {
        const int kb = kc * 64;
        __syncthreads();
        #pragma unroll
        for (int seg = tid; seg < 512; seg += 256) {
            const int row = seg >> 3, ko = (seg & 7) << 3;
            *(float4*)&sA[0][row][ko] =
                *(const float4*)&g_hs_hi[(size_t)(r0 + row) * 512 + kb + ko];
            *(float4*)&sA[1][row][ko] =
                *(const float4*)&g_hs_lo[(size_t)(r0 + row) * 512 + kb + ko];
            *(float4*)&sB[0][row][ko] =
                *(const float4*)&Bh[(size_t)(c0 + row) * ldb + kb + ko];
            *(float4*)&sB[1][row][ko] =
                *(const float4*)&Bl[(size_t)(c0 + row) * ldb + kb + ko];
        }
        __syncthreads();
        #pragma unroll
        for (int kk = 0; kk < 64; kk += 16) {
            uint32_t ah[4], al[4], bh[2][4], bl[2][4];
            ldm4(ah, aAddr + kk * 2);
            ldm4(al, aAddr + LOOFF + kk * 2);
            ldm4(bh[0], bAddr + kk * 2);
            ldm4(bh[1], bAddrP1 + kk * 2);
            ldm4(bl[0], bAddr + LOOFF + kk * 2);
            ldm4(bl[1], bAddrP1 + LOOFF + kk * 2);
            #pragma unroll
            for (int nt = 0; nt < 4; nt++) {
                const int p = nt >> 1, q = (nt & 1) * 2;
                mma_bf16(acc[nt], ah, bh[p][q], bh[p][q + 1]);   // hi*hi
                mma_bf16(acc[nt], ah, bl[p][q], bl[p][q + 1]);   // hi*lo
                mma_bf16(acc[nt], al, bh[p][q], bh[p][q + 1]);   // lo*hi
            }
        }
    }

    // epilogue: C-fragment -> global, fused bias
    const int rl = lane >> 2, cl = (lane & 3) * 2;
    const int gr = r0 + wr * 16 + rl;
    #pragma unroll
    for (int nt = 0; nt < 4; nt++) {
        const int gc = c0 + wc * 32 + nt * 8 + cl;
        float b0, b1;
        if (isX1) { b0 = Wd_b[gc]; b1 = Wd_b[gc + 1]; }
        else      { b0 = bih[gc] + bhh[gc]; b1 = bih[gc + 1] + bhh[gc + 1]; }
        C[(size_t)gr * ldc + gc]           = acc[nt][0] + b0;
        C[(size_t)gr * ldc + gc + 1]       = acc[nt][1] + b1;
        C[(size_t)(gr + 8) * ldc + gc]     = acc[nt][2] + b0;
        C[(size_t)(gr + 8) * ldc + gc + 1] = acc[nt][3] + b1;
    }
}

// ---------------- fp32 GEMM for y1 (runs once) ------------------------------
__device__ __forceinline__ void gemm_tile64(
    const float* __restrict__ A, int lda,
    const float* __restrict__ W, int ldw,
    float* __restrict__ C, int ldc, int r0, int c0, int K)
{
    __shared__ __align__(16) float As[2][16][68];
    __shared__ __align__(16) float Ws[2][16][68];
    const int t = threadIdx.x, ty = t >> 3, tx = t & 7;
    float acc[8][8];
    #pragma unroll
    for (int i = 0; i < 8; i++)
        #pragma unroll
        for (int j = 0; j < 8; j++) acc[i][j] = 0.0f;
    const float* Arow = A + (size_t)(r0 + t) * lda;
    const float* Wrow = W + (size_t)(c0 + t) * ldw;
    float4 ar[4], wr[4];
    #pragma unroll
    for (int q = 0; q < 4; q++) {
        ar[q] = *(const float4*)(Arow + q * 4);
        wr[q] = *(const float4*)(Wrow + q * 4);
    }
    #pragma unroll
    for (int q = 0; q < 4; q++) {
        As[0][q*4+0][t] = ar[q].x; As[0][q*4+1][t] = ar[q].y;
        As[0][q*4+2][t] = ar[q].z; As[0][q*4+3][t] = ar[q].w;
        Ws[0][q*4+0][t] = wr[q].x; Ws[0][q*4+1][t] = wr[q].y;
        Ws[0][q*4+2][t] = wr[q].z; Ws[0][q*4+3][t] = wr[q].w;
    }
    __syncthreads();
    const int nc = K >> 4;
    for (int c = 0; c < nc; c++) {
        const int cur = c & 1;
        if (c + 1 < nc) {
            const float* Ap = Arow + (c + 1) * 16;
            const float* Wp = Wrow + (c + 1) * 16;
            #pragma unroll
            for (int q = 0; q < 4; q++) {
                ar[q] = *(const float4*)(Ap + q * 4);
                wr[q] = *(const float4*)(Wp + q * 4);
            }
        }
        #pragma unroll
        for (int k = 0; k < 16; k++) {
            float a0[8], w0[8];
            *(float4*)&a0[0] = *(const float4*)&As[cur][k][ty * 8];
            *(float4*)&a0[4] = *(const float4*)&As[cur][k][ty * 8 + 4];
            *(float4*)&w0[0] = *(const float4*)&Ws[cur][k][tx * 8];
            *(float4*)&w0[4] = *(const float4*)&Ws[cur][k][tx * 8 + 4];
            #pragma unroll
            for (int i = 0; i < 8; i++)
                #pragma unroll
                for (int j = 0; j < 8; j++)
                    acc[i][j] += a0[i] * w0[j];
        }
        if (c + 1 < nc) {
            const int nxt = cur ^ 1;
            #pragma unroll
            for (int q = 0; q < 4; q++) {
                As[nxt][q*4+0][t] = ar[q].x; As[nxt][q*4+1][t] = ar[q].y;
                As[nxt][q*4+2][t] = ar[q].z; As[nxt][q*4+3][t] = ar[q].w;
                Ws[nxt][q*4+0][t] = wr[q].x; Ws[nxt][q*4+1][t] = wr[q].y;
                Ws[nxt][q*4+2][t] = wr[q].z; Ws[nxt][q*4+3][t] = wr[q].w;
            }
            __syncthreads();
        }
    }
    #pragma unroll
    for (int i = 0; i < 8; i++) {
        const int row = r0 + ty * 8 + i;
        #pragma unroll
        for (int j = 0; j < 8; j += 4)
            *(float4*)&C[(size_t)row * ldc + c0 + tx * 8 + j] =
                make_float4(acc[i][j], acc[i][j+1], acc[i][j+2], acc[i][j+3]);
    }
}
__global__ void __launch_bounds__(64) y1_gemm_kernel(const float* __restrict__ enc,
                                                     const float* __restrict__ Ud_w) {
    gemm_tile64(enc, Mn, Ud_w, Mn, g_y1, Mn, blockIdx.x * 64, blockIdx.y * 64, Mn);
}

// ---------------- fused attention + LSTM step (one CTA per batch row) -------
__global__ void __launch_bounds__(256) attn_step_kernel(
        const float* __restrict__ enc, const float* __restrict__ y,
        const float* __restrict__ vd_w, const float* __restrict__ wt_w,
        const float* __restrict__ wt_b, const float* __restrict__ Wih,
        int t_step) {
    const int b = blockIdx.x;
    const int tid = threadIdx.x;          // 256 threads, 8 warps
    const int w = tid >> 5, l = tid & 31;

    __shared__ float x1s[Mn];
    __shared__ float vs[Mn];
    __shared__ float ls[Tn];
    __shared__ float red8[8];
    __shared__ float s_ytil;

    x1s[tid] = g_x1[b * Mn + tid];
    vs[tid]  = vd_w[tid];
    __syncthreads();

    // logits l[t] = sum_m tanh(x1[m] + y1[b,t,m]) * v[m]
    #pragma unroll
    for (int idx = 0; idx < 8; idx++) {
        int t = w * 8 + idx;
        const float* y1row = &g_y1[((size_t)b * Tn + t) * Mn];
        float sum = 0.0f;
        #pragma unroll
        for (int j = 0; j < 8; j++) {
            int m = l + 32 * j;
            sum += tanh_acc(x1s[m] + y1row[m]) * vs[m];
        }
        #pragma unroll
        for (int o = 16; o > 0; o >>= 1) sum += __shfl_xor_sync(0xffffffffu, sum, o);
        if (l == 0) ls[t] = sum;
    }
    __syncthreads();

    if (w == 0) {                          // softmax over T=64
        float a = ls[l], c = ls[l + 32];
        float mx = fmaxf(a, c);
        #pragma unroll
        for (int o = 16; o > 0; o >>= 1) mx = fmaxf(mx, __shfl_xor_sync(0xffffffffu, mx, o));
        float e0 = __expf(a - mx), e1 = __expf(c - mx);
        float ts = e0 + e1;
        #pragma unroll
        for (int o = 16; o > 0; o >>= 1) ts += __shfl_xor_sync(0xffffffffu, ts, o);
        float inv = __fdividef(1.0f, ts);
        ls[l]      = e0 * inv;
        ls[l + 32] = e1 * inv;
    }
    __syncthreads();

    // context
    const int m = tid;
    float acc = 0.0f;
    const float* encb = &enc[(size_t)b * Tn * Mn];
    #pragma unroll 8
    for (int t = 0; t < Tn; t++) acc += ls[t] * encb[t * Mn + m];
    g_ct[b * Mn + m] = acc;

    float tot = block_reduce_256(acc * wt_w[m], red8);
    if (tid == 0)
        s_ytil = tot + y[b * Tn + t_step] * wt_w[Mn] + wt_b[0];
    __syncthreads();
    const float ytil = s_ytil;

    // LSTM cell (i,f,g,o; biases folded into g_gh)
    const float* gh = &g_gh[(size_t)b * G4n];
    float ig = gh[tid]          + ytil * Wih[tid];
    float fg = gh[tid + Pn]     + ytil * Wih[tid + Pn];
    float gg = gh[tid + 2*Pn]   + ytil * Wih[tid + 2*Pn];
    float og = gh[tid + 3*Pn]   + ytil * Wih[tid + 3*Pn];
    float so = g_hs[b * 512 + 256 + tid];
    float cn = sigm(fg) * so + sigm(ig) * tanh_acc(gg);
    float hn = sigm(og) * tanh_acc(cn);
    g_hs[b * 512 + 256 + tid] = cn;
    g_hs[b * 512 + tid]       = hn;
    split_store(hn, &g_hs_hi[b * 512 + tid],       &g_hs_lo[b * 512 + tid]);
    split_store(cn, &g_hs_hi[b * 512 + 256 + tid], &g_hs_lo[b * 512 + 256 + tid]);
}

// ---------------- y_Tp1 head (warp per batch row) ---------------------------
__global__ void __launch_bounds__(256) head1_kernel(float* __restrict__ out) {
    int w = threadIdx.x >> 5, l = threadIdx.x & 31;
    int b = blockIdx.x * 8 + w;
    float sum = 0.0f;
    #pragma unroll
    for (int j = l; j < Pn; j += 32)
        sum += g_hs[b * 512 + j] * g_u[j] + g_ct[b * Mn + j] * g_u[Pn + j];
    #pragma unroll
    for (int o = 16; o > 0; o >>= 1) sum += __shfl_xor_sync(0xffffffffu, sum, o);
    if (l == 0) out[b] = sum + g_u[2 * Pn];
}

// ---------------- extra step e (0 or 1): y_til, LSTM, head ------------------
__global__ void __launch_bounds__(256) extra_step_kernel(
        const float* __restrict__ tar, const int* __restrict__ trainp,
        const float* __restrict__ wt_w, const float* __restrict__ wt_b,
        const float* __restrict__ Wih, float* __restrict__ out, int e) {
    const int b = blockIdx.x, tid = threadIdx.x;
    __shared__ float red8[8];
    __shared__ float s_ytil;

    const float ct = g_ct[b * Mn + tid];
    float dct = block_reduce_256(ct * wt_w[tid], red8);
    if (tid == 0) {
        int train = (trainp[0] != 0);
        float inp = train ? tar[b * 2 + e] : out[e * Bn + b];
        s_ytil = dct + inp * wt_w[Mn] + wt_b[0];
    }
    __syncthreads();
    const float ytil = s_ytil;

    const float* gh = &g_gh[(size_t)b * G4n];
    float ig = gh[tid]          + ytil * Wih[tid];
    float fg = gh[tid + Pn]     + ytil * Wih[tid + Pn];
    float gg = gh[tid + 2*Pn]   + ytil * Wih[tid + 2*Pn];
    float og = gh[tid + 3*Pn]   + ytil * Wih[tid + 3*Pn];
    float so = g_hs[b * 512 + 256 + tid];
    float cn = sigm(fg) * so + sigm(ig) * tanh_acc(gg);
    float hn = sigm(og) * tanh_acc(cn);
    g_hs[b * 512 + 256 + tid] = cn;
    g_hs[b * 512 + tid]       = hn;
    split_store(hn, &g_hs_hi[b * 512 + tid],       &g_hs_lo[b * 512 + tid]);
    split_store(cn, &g_hs_hi[b * 512 + 256 + tid], &g_hs_lo[b * 512 + 256 + tid]);

    float tot = block_reduce_256(hn * g_u[tid] + ct * g_u[Pn + tid], red8);
    if (tid == 0) out[(e + 1) * Bn + b] = tot + g_u[2 * Pn];
}

// ---------------- launcher --------------------------------------------------
extern "C" void kernel_launch(void* const* d_in, const int* in_sizes, int n_in,
                              void* d_out, int out_size) {
    const float* enc   = (const float*)d_in[0];
    const float* y     = (const float*)d_in[1];
    const float* tar   = (const float*)d_in[2];
    const int*   train = (const int*)  d_in[3];
    const float* Wd_w  = (const float*)d_in[4];
    const float* Wd_b  = (const float*)d_in[5];
    const float* Ud_w  = (const float*)d_in[6];
    const float* vd_w  = (const float*)d_in[7];
    const float* wt_w  = (const float*)d_in[8];
    const float* wt_b  = (const float*)d_in[9];
    const float* Wy_w  = (const float*)d_in[10];
    const float* Wy_b  = (const float*)d_in[11];
    const float* vy_w  = (const float*)d_in[12];
    const float* vy_b  = (const float*)d_in[13];
    const float* Wih   = (const float*)d_in[14];
    const float* Whh   = (const float*)d_in[15];
    const float* bih   = (const float*)d_in[16];
    const float* bhh   = (const float*)d_in[17];
    float* out = (float*)d_out;

    init_state_kernel<<<Bn, 512>>>();
    conv_weights_kernel<<<1024, 256>>>(Wd_w, Whh);
    compute_u_kernel<<<1, 512>>>(vy_w, Wy_w, Wy_b, vy_b);
    y1_gemm_kernel<<<dim3(Bn * Tn / 64, Mn / 64), 64>>>(enc, Ud_w);

    for (int t = 0; t < Tn; t++) {
        step_gemm_mma<<<dim3(8, 20), 256>>>(Wd_b, bih, bhh, 0);
        attn_step_kernel<<<Bn, 256>>>(enc, y, vd_w, wt_w, wt_b, Wih, t);
    }

    head1_kernel<<<Bn / 8, 256>>>(out);

    for (int e = 0; e < 2; e++) {
        step_gemm_mma<<<dim3(8, 16), 256>>>(Wd_b, bih, bhh, 1);
        extra_step_kernel<<<Bn, 256>>>(tar, train, wt_w, wt_b, Wih, out, e);
    }
}

// round 7
// speedup vs baseline: 2.6205x; 1.1419x over previous
#include <cuda_runtime.h>
#include <cuda_bf16.h>
#include <cstdint>

#define Bn   512
#define Tn   64
#define Mn   256
#define Pn   256
#define G4n  1024

// ---------------- device-global scratch (allocation-free) -------------------
__device__ __align__(256) float g_y1 [Bn * Tn * Mn]; // enc @ Ud^T (33.5 MB)
__device__ __align__(256) float g_hs [Bn * 2 * Pn];  // [h | s], lda=512 (fp32 truth)
__device__ __align__(256) float g_ct [Bn * Mn];
__device__ __align__(256) float g_x1 [Bn * Mn];      // Wd GEMM out (+Wd_b)
__device__ __align__(256) float g_gh [Bn * G4n];     // Whh GEMM out (+bih+bhh)
__device__ __align__(256) float g_u  [2 * Pn + 1];

// bf16 hi/lo split operands for tensor-core GEMMs
__device__ __align__(256) __nv_bfloat16 g_hs_hi [Bn * 2 * Pn];
__device__ __align__(256) __nv_bfloat16 g_hs_lo [Bn * 2 * Pn];
__device__ __align__(256) __nv_bfloat16 g_Wd_hi [Mn * 2 * Pn];
__device__ __align__(256) __nv_bfloat16 g_Wd_lo [Mn * 2 * Pn];
__device__ __align__(256) __nv_bfloat16 g_Whh_hi[G4n * Pn];
__device__ __align__(256) __nv_bfloat16 g_Whh_lo[G4n * Pn];
__device__ __align__(256) __nv_bfloat16 g_Ud_hi [Mn * Mn];
__device__ __align__(256) __nv_bfloat16 g_Ud_lo [Mn * Mn];
__device__ __align__(256) __nv_bfloat16 g_enc_hi[Bn * Tn * Mn];
__device__ __align__(256) __nv_bfloat16 g_enc_lo[Bn * Tn * Mn];

// ---------------- math helpers ---------------------------------------------
__device__ __forceinline__ float tanh_acc(float x) {        // accurate (LSTM)
    float e = __expf(2.0f * x);
    return 1.0f - __fdividef(2.0f, e + 1.0f);
}
__device__ __forceinline__ float tanh_fast(float x) {       // MUFU.TANH (attn)
    float r;
    asm("tanh.approx.f32 %0, %1;" : "=f"(r) : "f"(x));
    return r;
}
__device__ __forceinline__ float sigm(float x) {
    return __fdividef(1.0f, 1.0f + __expf(-x));
}
__device__ __forceinline__ float block_reduce_256(float v, float* red8) {
    #pragma unroll
    for (int o = 16; o > 0; o >>= 1) v += __shfl_xor_sync(0xffffffffu, v, o);
    int w = threadIdx.x >> 5, l = threadIdx.x & 31;
    __syncthreads();
    if (l == 0) red8[w] = v;
    __syncthreads();
    float r = red8[0];
    #pragma unroll
    for (int i = 1; i < 8; i++) r += red8[i];
    return r;
}
__device__ __forceinline__ void split_store(float v, __nv_bfloat16* hi,
                                            __nv_bfloat16* lo) {
    __nv_bfloat16 h = __float2bfloat16(v);
    *hi = h;
    *lo = __float2bfloat16(v - __bfloat162float(h));
}

// ---------------- mma / ldmatrix / cp.async primitives ----------------------
__device__ __forceinline__ void ldm4(uint32_t* r, uint32_t addr) {
    asm volatile("ldmatrix.sync.aligned.m8n8.x4.shared.b16 {%0,%1,%2,%3}, [%4];"
        : "=r"(r[0]), "=r"(r[1]), "=r"(r[2]), "=r"(r[3]) : "r"(addr));
}
__device__ __forceinline__ void mma_bf16(float* d, const uint32_t* a,
                                         uint32_t b0, uint32_t b1) {
    asm volatile(
        "mma.sync.aligned.m16n8k16.row.col.f32.bf16.bf16.f32 "
        "{%0,%1,%2,%3}, {%4,%5,%6,%7}, {%8,%9}, {%0,%1,%2,%3};"
        : "+f"(d[0]), "+f"(d[1]), "+f"(d[2]), "+f"(d[3])
        : "r"(a[0]), "r"(a[1]), "r"(a[2]), "r"(a[3]), "r"(b0), "r"(b1));
}
__device__ __forceinline__ void cpa16(uint32_t dst, const void* src) {
    asm volatile("cp.async.ca.shared.global [%0], [%1], 16;\n"
                 :: "r"(dst), "l"(src));
}
__device__ __forceinline__ void cpa_commit() {
    asm volatile("cp.async.commit_group;\n");
}

// ---------------- init / weight & activation conversion ---------------------
__global__ void init_state_kernel() {
    int i = blockIdx.x * 512 + threadIdx.x;
    g_hs[i] = 0.0f;
    g_hs_hi[i] = __float2bfloat16(0.0f);
    g_hs_lo[i] = __float2bfloat16(0.0f);
}
__global__ void conv_weights_kernel(const float* __restrict__ Wd,
                                    const float* __restrict__ Whh,
                                    const float* __restrict__ Ud) {
    int i = blockIdx.x * 256 + threadIdx.x;
    if (i < Mn * 2 * Pn) split_store(Wd[i], &g_Wd_hi[i], &g_Wd_lo[i]);
    if (i < G4n * Pn)    split_store(Whh[i], &g_Whh_hi[i], &g_Whh_lo[i]);
    if (i < Mn * Mn)     split_store(Ud[i],  &g_Ud_hi[i],  &g_Ud_lo[i]);
}
__global__ void conv_enc_kernel(const float* __restrict__ enc) {
    size_t i = ((size_t)blockIdx.x * 256 + threadIdx.x) * 4;
    float4 v = *(const float4*)&enc[i];
    __nv_bfloat16 h[4], l[4];
    float vv[4] = {v.x, v.y, v.z, v.w};
    #pragma unroll
    for (int q = 0; q < 4; q++) {
        h[q] = __float2bfloat16(vv[q]);
        l[q] = __float2bfloat16(vv[q] - __bfloat162float(h[q]));
    }
    __nv_bfloat162 ph0, ph1, pl0, pl1;
    ph0.x = h[0]; ph0.y = h[1]; ph1.x = h[2]; ph1.y = h[3];
    pl0.x = l[0]; pl0.y = l[1]; pl1.x = l[2]; pl1.y = l[3];
    *(__nv_bfloat162*)&g_enc_hi[i]     = ph0;
    *(__nv_bfloat162*)&g_enc_hi[i + 2] = ph1;
    *(__nv_bfloat162*)&g_enc_lo[i]     = pl0;
    *(__nv_bfloat162*)&g_enc_lo[i + 2] = pl1;
}

// ---------------- fold head: u = vy_w @ Wy_w, uc = vy_w·Wy_b + vy_b ---------
__global__ void compute_u_kernel(const float* __restrict__ vy_w,
                                 const float* __restrict__ Wy_w,
                                 const float* __restrict__ Wy_b,
                                 const float* __restrict__ vy_b) {
    int j = threadIdx.x;            // 512 threads
    float s = 0.0f;
    #pragma unroll 4
    for (int n = 0; n < Pn; n++) s += vy_w[n] * Wy_w[n * 512 + j];
    g_u[j] = s;
    __shared__ float red[16];
    float v = (j < Pn) ? vy_w[j] * Wy_b[j] : 0.0f;
    #pragma unroll
    for (int o = 16; o > 0; o >>= 1) v += __shfl_xor_sync(0xffffffffu, v, o);
    int w = j >> 5, l = j & 31;
    if (l == 0) red[w] = v;
    __syncthreads();
    if (j == 0) {
        float r = 0.0f;
        #pragma unroll
        for (int i = 0; i < 16; i++) r += red[i];
        g_u[2 * Pn] = r + vy_b[0];
    }
}

// ---------------- split-bf16 MMA 64x64 tile, cp.async double-buffered -------
// C[r0+i, c0+j] = sum_k A[r,k]*B[c,k] (+bias). 256 threads, 8 warps (4x2).
// Planes per buffer: 0=A_hi 1=A_lo 2=B_hi 3=B_lo. K-chunk = 32, stride 40.
#define ST    40
#define PLB   (64 * ST * 2)          // bytes per plane  (5120)
#define BUFB  (4 * PLB)              // bytes per buffer (20480)

__device__ __forceinline__ void mma_tile64(
    const __nv_bfloat16* __restrict__ Ah, const __nv_bfloat16* __restrict__ Al,
    int lda,
    const __nv_bfloat16* __restrict__ Bh, const __nv_bfloat16* __restrict__ Bl,
    int ldb,
    float* __restrict__ C, int ldc, int r0, int c0, int K,
    const float* __restrict__ b1, const float* __restrict__ b2)
{
    __shared__ __align__(16) __nv_bfloat16 sm[2 * 4 * 64 * ST];
    const int tid = threadIdx.x;
    const int wid = tid >> 5, lane = tid & 31;
    const int wr = wid & 3, wc = wid >> 2;
    const uint32_t sb = (uint32_t)__cvta_generic_to_shared(sm);

    // cp.async source/dest mapping: each thread one 16B segment per plane
    const int row = tid >> 2, ko = (tid & 3) * 8;
    const __nv_bfloat16* pAh = Ah + (size_t)(r0 + row) * lda + ko;
    const __nv_bfloat16* pAl = Al + (size_t)(r0 + row) * lda + ko;
    const __nv_bfloat16* pBh = Bh + (size_t)(c0 + row) * ldb + ko;
    const __nv_bfloat16* pBl = Bl + (size_t)(c0 + row) * ldb + ko;
    const uint32_t dA = sb + (uint32_t)(row * ST + ko) * 2;

    float acc[4][4];
    #pragma unroll
    for (int n = 0; n < 4; n++)
        #pragma unroll
        for (int i = 0; i < 4; i++) acc[n][i] = 0.0f;

    // ldmatrix fragment addresses (buffer 0)
    const int grp = lane >> 3, lr = lane & 7;
    const uint32_t aAddr = sb +
        (uint32_t)((wr * 16 + ((grp & 1) << 3) + lr) * ST + ((grp >> 1) << 3)) * 2;
    const uint32_t bAddr = sb + 2 * PLB +
        (uint32_t)((wc * 32 + ((grp >> 1) << 3) + lr) * ST + ((grp & 1) << 3)) * 2;

    const int nch = K >> 5;
    // preload chunk 0
    {
        cpa16(dA,            pAh);
        cpa16(dA + PLB,      pAl);
        cpa16(dA + 2 * PLB,  pBh);
        cpa16(dA + 3 * PLB,  pBl);
        cpa_commit();
    }
    for (int c = 0; c < nch; c++) {
        if (c + 1 < nch) {
            const int kb = (c + 1) * 32;
            const uint32_t d = dA + ((c + 1) & 1) * BUFB;
            cpa16(d,           pAh + kb);
            cpa16(d + PLB,     pAl + kb);
            cpa16(d + 2 * PLB, pBh + kb);
            cpa16(d + 3 * PLB, pBl + kb);
            cpa_commit();
            asm volatile("cp.async.wait_group 1;\n");
        } else {
            asm volatile("cp.async.wait_group 0;\n");
        }
        __syncthreads();
        const uint32_t bo = (c & 1) * BUFB;
        #pragma unroll
        for (int kk = 0; kk < 32; kk += 16) {
            uint32_t ah[4], al[4], bh[2][4], bl[2][4];
            ldm4(ah,   aAddr + bo + kk * 2);
            ldm4(al,   aAddr + bo + PLB + kk * 2);
            ldm4(bh[0], bAddr + bo + kk * 2);
            ldm4(bh[1], bAddr + bo + 16 * ST * 2 + kk * 2);
            ldm4(bl[0], bAddr + bo + PLB + kk * 2);
            ldm4(bl[1], bAddr + bo + PLB + 16 * ST * 2 + kk * 2);
            #pragma unroll
            for (int nt = 0; nt < 4; nt++) {
                const int p = nt >> 1, q = (nt & 1) * 2;
                mma_bf16(acc[nt], ah, bh[p][q], bh[p][q + 1]);   // hi*hi
                mma_bf16(acc[nt], ah, bl[p][q], bl[p][q + 1]);   // hi*lo
                mma_bf16(acc[nt], al, bh[p][q], bh[p][q + 1]);   // lo*hi
            }
        }
        __syncthreads();
    }

    // epilogue: C-fragment -> global, fused bias
    const int rl = lane >> 2, cl = (lane & 3) * 2;
    const int gr = r0 + wr * 16 + rl;
    #pragma unroll
    for (int nt = 0; nt < 4; nt++) {
        const int gc = c0 + wc * 32 + nt * 8 + cl;
        float v0 = 0.0f, v1 = 0.0f;
        if (b1) { v0 += b1[gc]; v1 += b1[gc + 1]; }
        if (b2) { v0 += b2[gc]; v1 += b2[gc + 1]; }
        C[(size_t)gr * ldc + gc]           = acc[nt][0] + v0;
        C[(size_t)gr * ldc + gc + 1]       = acc[nt][1] + v1;
        C[(size_t)(gr + 8) * ldc + gc]     = acc[nt][2] + v0;
        C[(size_t)(gr + 8) * ldc + gc + 1] = acc[nt][3] + v1;
    }
}

// y1 = enc(32768x256) @ Ud^T(256x256)
__global__ void __launch_bounds__(256) y1_mma_kernel() {
    mma_tile64(g_enc_hi, g_enc_lo, Mn, g_Ud_hi, g_Ud_lo, Mn,
               g_y1, Mn, blockIdx.x * 64, blockIdx.y * 64, Mn,
               nullptr, nullptr);
}

// per-step GEMMs: ytile<4: x1 = hs@Wd^T (K=512); else gh = h@Whh^T (K=256)
__global__ void __launch_bounds__(256) step_gemm_mma(
        const float* __restrict__ Wd_b, const float* __restrict__ bih,
        const float* __restrict__ bhh, int ghonly) {
    const int ytile = blockIdx.y + (ghonly ? 4 : 0);
    const int r0 = blockIdx.x * 64;
    if (ytile < 4) {
        mma_tile64(g_hs_hi, g_hs_lo, 512, g_Wd_hi, g_Wd_lo, 512,
                   g_x1, Mn, r0, ytile * 64, 512, Wd_b, nullptr);
    } else {
        mma_tile64(g_hs_hi, g_hs_lo, 512, g_Whh_hi, g_Whh_lo, 256,
                   g_gh, G4n, r0, (ytile - 4) * 64, 256, bih, bhh);
    }
}

// ---------------- fused attention + LSTM step (one CTA per batch row) -------
__global__ void __launch_bounds__(256) attn_step_kernel(
        const float* __restrict__ enc, const float* __restrict__ y,
        const float* __restrict__ vd_w, const float* __restrict__ wt_w,
        const float* __restrict__ wt_b, const float* __restrict__ Wih,
        int t_step) {
    const int b = blockIdx.x;
    const int tid = threadIdx.x;          // 256 threads, 8 warps
    const int w = tid >> 5, l = tid & 31;

    __shared__ float x1s[Mn];
    __shared__ float vs[Mn];
    __shared__ float ls[Tn];
    __shared__ float red8[8];
    __shared__ float s_ytil;

    x1s[tid] = g_x1[b * Mn + tid];
    vs[tid]  = vd_w[tid];
    __syncthreads();

    // logits l[t] = sum_m tanh(x1[m] + y1[b,t,m]) * v[m]   (MUFU.TANH)
    #pragma unroll
    for (int idx = 0; idx < 8; idx++) {
        int t = w * 8 + idx;
        const float* y1row = &g_y1[((size_t)b * Tn + t) * Mn];
        float sum = 0.0f;
        #pragma unroll
        for (int j = 0; j < 8; j++) {
            int m = l + 32 * j;
            sum += tanh_fast(x1s[m] + y1row[m]) * vs[m];
        }
        #pragma unroll
        for (int o = 16; o > 0; o >>= 1) sum += __shfl_xor_sync(0xffffffffu, sum, o);
        if (l == 0) ls[t] = sum;
    }
    __syncthreads();

    if (w == 0) {                          // softmax over T=64
        float a = ls[l], c = ls[l + 32];
        float mx = fmaxf(a, c);
        #pragma unroll
        for (int o = 16; o > 0; o >>= 1) mx = fmaxf(mx, __shfl_xor_sync(0xffffffffu, mx, o));
        float e0 = __expf(a - mx), e1 = __expf(c - mx);
        float ts = e0 + e1;
        #pragma unroll
        for (int o = 16; o > 0; o >>= 1) ts += __shfl_xor_sync(0xffffffffu, ts, o);
        float inv = __fdividef(1.0f, ts);
        ls[l]      = e0 * inv;
        ls[l + 32] = e1 * inv;
    }
    __syncthreads();

    // context
    const int m = tid;
    float acc = 0.0f;
    const float* encb = &enc[(size_t)b * Tn * Mn];
    #pragma unroll 8
    for (int t = 0; t < Tn; t++) acc += ls[t] * encb[t * Mn + m];
    g_ct[b * Mn + m] = acc;

    float tot = block_reduce_256(acc * wt_w[m], red8);
    if (tid == 0)
        s_ytil = tot + y[b * Tn + t_step] * wt_w[Mn] + wt_b[0];
    __syncthreads();
    const float ytil = s_ytil;

    // LSTM cell (i,f,g,o; biases folded into g_gh) — accurate activations
    const float* gh = &g_gh[(size_t)b * G4n];
    float ig = gh[tid]          + ytil * Wih[tid];
    float fg = gh[tid + Pn]     + ytil * Wih[tid + Pn];
    float gg = gh[tid + 2*Pn]   + ytil * Wih[tid + 2*Pn];
    float og = gh[tid + 3*Pn]   + ytil * Wih[tid + 3*Pn];
    float so = g_hs[b * 512 + 256 + tid];
    float cn = sigm(fg) * so + sigm(ig) * tanh_acc(gg);
    float hn = sigm(og) * tanh_acc(cn);
    g_hs[b * 512 + 256 + tid] = cn;
    g_hs[b * 512 + tid]       = hn;
    split_store(hn, &g_hs_hi[b * 512 + tid],       &g_hs_lo[b * 512 + tid]);
    split_store(cn, &g_hs_hi[b * 512 + 256 + tid], &g_hs_lo[b * 512 + 256 + tid]);
}

// ---------------- y_Tp1 head (warp per batch row) ---------------------------
__global__ void __launch_bounds__(256) head1_kernel(float* __restrict__ out) {
    int w = threadIdx.x >> 5, l = threadIdx.x & 31;
    int b = blockIdx.x * 8 + w;
    float sum = 0.0f;
    #pragma unroll
    for (int j = l; j < Pn; j += 32)
        sum += g_hs[b * 512 + j] * g_u[j] + g_ct[b * Mn + j] * g_u[Pn + j];
    #pragma unroll
    for (int o = 16; o > 0; o >>= 1) sum += __shfl_xor_sync(0xffffffffu, sum, o);
    if (l == 0) out[b] = sum + g_u[2 * Pn];
}

// ---------------- extra step e (0 or 1): y_til, LSTM, head ------------------
__global__ void __launch_bounds__(256) extra_step_kernel(
        const float* __restrict__ tar, const int* __restrict__ trainp,
        const float* __restrict__ wt_w, const float* __restrict__ wt_b,
        const float* __restrict__ Wih, float* __restrict__ out, int e) {
    const int b = blockIdx.x, tid = threadIdx.x;
    __shared__ float red8[8];
    __shared__ float s_ytil;

    const float ct = g_ct[b * Mn + tid];
    float dct = block_reduce_256(ct * wt_w[tid], red8);
    if (tid == 0) {
        int train = (trainp[0] != 0);
        float inp = train ? tar[b * 2 + e] : out[e * Bn + b];
        s_ytil = dct + inp * wt_w[Mn] + wt_b[0];
    }
    __syncthreads();
    const float ytil = s_ytil;

    const float* gh = &g_gh[(size_t)b * G4n];
    float ig = gh[tid]          + ytil * Wih[tid];
    float fg = gh[tid + Pn]     + ytil * Wih[tid + Pn];
    float gg = gh[tid + 2*Pn]   + ytil * Wih[tid + 2*Pn];
    float og = gh[tid + 3*Pn]   + ytil * Wih[tid + 3*Pn];
    float so = g_hs[b * 512 + 256 + tid];
    float cn = sigm(fg) * so + sigm(ig) * tanh_acc(gg);
    float hn = sigm(og) * tanh_acc(cn);
    g_hs[b * 512 + 256 + tid] = cn;
    g_hs[b * 512 + tid]       = hn;
    split_store(hn, &g_hs_hi[b * 512 + tid],       &g_hs_lo[b * 512 + tid]);
    split_store(cn, &g_hs_hi[b * 512 + 256 + tid], &g_hs_lo[b * 512 + 256 + tid]);

    float tot = block_reduce_256(hn * g_u[tid] + ct * g_u[Pn + tid], red8);
    if (tid == 0) out[(e + 1) * Bn + b] = tot + g_u[2 * Pn];
}

// ---------------- launcher --------------------------------------------------
extern "C" void kernel_launch(void* const* d_in, const int* in_sizes, int n_in,
                              void* d_out, int out_size) {
    const float* enc   = (const float*)d_in[0];
    const float* y     = (const float*)d_in[1];
    const float* tar   = (const float*)d_in[2];
    const int*   train = (const int*)  d_in[3];
    const float* Wd_w  = (const float*)d_in[4];
    const float* Wd_b  = (const float*)d_in[5];
    const float* Ud_w  = (const float*)d_in[6];
    const float* vd_w  = (const float*)d_in[7];
    const float* wt_w  = (const float*)d_in[8];
    const float* wt_b  = (const float*)d_in[9];
    const float* Wy_w  = (const float*)d_in[10];
    const float* Wy_b  = (const float*)d_in[11];
    const float* vy_w  = (const float*)d_in[12];
    const float* vy_b  = (const float*)d_in[13];
    const float* Wih   = (const float*)d_in[14];
    const float* Whh   = (const float*)d_in[15];
    const float* bih   = (const float*)d_in[16];
    const float* bhh   = (const float*)d_in[17];
    float* out = (float*)d_out;

    init_state_kernel<<<Bn, 512>>>();
    conv_weights_kernel<<<1024, 256>>>(Wd_w, Whh, Ud_w);
    conv_enc_kernel<<<8192, 256>>>(enc);
    compute_u_kernel<<<1, 512>>>(vy_w, Wy_w, Wy_b, vy_b);
    y1_mma_kernel<<<dim3(512, 4), 256>>>();

    for (int t = 0; t < Tn; t++) {
        step_gemm_mma<<<dim3(8, 20), 256>>>(Wd_b, bih, bhh, 0);
        attn_step_kernel<<<Bn, 256>>>(enc, y, vd_w, wt_w, wt_b, Wih, t);
    }

    head1_kernel<<<Bn / 8, 256>>>(out);

    for (int e = 0; e < 2; e++) {
        step_gemm_mma<<<dim3(8, 16), 256>>>(Wd_b, bih, bhh, 1);
        extra_step_kernel<<<Bn, 256>>>(tar, train, wt_w, wt_b, Wih, out, e);
    }
}

// round 8
// speedup vs baseline: 3.1150x; 1.1887x over previous
#include <cuda_runtime.h>
#include <cuda_bf16.h>
#include <cstdint>

#define Bn   512
#define Tn   64
#define Mn   256
#define Pn   256
#define G4n  1024

// ---------------- device-global scratch (allocation-free) -------------------
__device__ __align__(256) float g_y1 [Bn * Tn * Mn]; // enc @ Ud^T (33.5 MB)
__device__ __align__(256) float g_hs [Bn * 2 * Pn];  // [h | s], lda=512 (fp32 truth)
__device__ __align__(256) float g_ct [Bn * Mn];
__device__ __align__(256) float g_x1p0[Bn * Mn];     // split-K partials of x1
__device__ __align__(256) float g_x1p1[Bn * Mn];
__device__ __align__(256) float g_ghp0[Bn * G4n];    // split-K partials of gh
__device__ __align__(256) float g_ghp1[Bn * G4n];
__device__ __align__(256) float g_u  [2 * Pn + 1];

// bf16 hi/lo split operands for tensor-core GEMMs
__device__ __align__(256) __nv_bfloat16 g_hs_hi [Bn * 2 * Pn];
__device__ __align__(256) __nv_bfloat16 g_hs_lo [Bn * 2 * Pn];
__device__ __align__(256) __nv_bfloat16 g_Wd_hi [Mn * 2 * Pn];
__device__ __align__(256) __nv_bfloat16 g_Wd_lo [Mn * 2 * Pn];
__device__ __align__(256) __nv_bfloat16 g_Whh_hi[G4n * Pn];
__device__ __align__(256) __nv_bfloat16 g_Whh_lo[G4n * Pn];
__device__ __align__(256) __nv_bfloat16 g_Ud_hi [Mn * Mn];
__device__ __align__(256) __nv_bfloat16 g_Ud_lo [Mn * Mn];
__device__ __align__(256) __nv_bfloat16 g_enc_hi[Bn * Tn * Mn];
__device__ __align__(256) __nv_bfloat16 g_enc_lo[Bn * Tn * Mn];

// ---------------- math helpers ---------------------------------------------
__device__ __forceinline__ float tanh_acc(float x) {        // accurate (LSTM)
    float e = __expf(2.0f * x);
    return 1.0f - __fdividef(2.0f, e + 1.0f);
}
__device__ __forceinline__ float tanh_fast(float x) {       // MUFU.TANH (attn)
    float r;
    asm("tanh.approx.f32 %0, %1;" : "=f"(r) : "f"(x));
    return r;
}
__device__ __forceinline__ float sigm(float x) {
    return __fdividef(1.0f, 1.0f + __expf(-x));
}
__device__ __forceinline__ float block_reduce_256(float v, float* red8) {
    #pragma unroll
    for (int o = 16; o > 0; o >>= 1) v += __shfl_xor_sync(0xffffffffu, v, o);
    int w = threadIdx.x >> 5, l = threadIdx.x & 31;
    __syncthreads();
    if (l == 0) red8[w] = v;
    __syncthreads();
    float r = red8[0];
    #pragma unroll
    for (int i = 1; i < 8; i++) r += red8[i];
    return r;
}
__device__ __forceinline__ void split_store(float v, __nv_bfloat16* hi,
                                            __nv_bfloat16* lo) {
    __nv_bfloat16 h = __float2bfloat16(v);
    *hi = h;
    *lo = __float2bfloat16(v - __bfloat162float(h));
}

// ---------------- mma / ldmatrix / cp.async primitives ----------------------
__device__ __forceinline__ void ldm4(uint32_t* r, uint32_t addr) {
    asm volatile("ldmatrix.sync.aligned.m8n8.x4.shared.b16 {%0,%1,%2,%3}, [%4];"
        : "=r"(r[0]), "=r"(r[1]), "=r"(r[2]), "=r"(r[3]) : "r"(addr));
}
__device__ __forceinline__ void mma_bf16(float* d, const uint32_t* a,
                                         uint32_t b0, uint32_t b1) {
    asm volatile(
        "mma.sync.aligned.m16n8k16.row.col.f32.bf16.bf16.f32 "
        "{%0,%1,%2,%3}, {%4,%5,%6,%7}, {%8,%9}, {%0,%1,%2,%3};"
        : "+f"(d[0]), "+f"(d[1]), "+f"(d[2]), "+f"(d[3])
        : "r"(a[0]), "r"(a[1]), "r"(a[2]), "r"(a[3]), "r"(b0), "r"(b1));
}
__device__ __forceinline__ void cpa16(uint32_t dst, const void* src) {
    asm volatile("cp.async.ca.shared.global [%0], [%1], 16;\n"
                 :: "r"(dst), "l"(src));
}
__device__ __forceinline__ void cpa_commit() {
    asm volatile("cp.async.commit_group;\n");
}

// ---------------- init / weight & activation conversion ---------------------
__global__ void init_state_kernel() {
    int i = blockIdx.x * 512 + threadIdx.x;
    g_hs[i] = 0.0f;
    g_hs_hi[i] = __float2bfloat16(0.0f);
    g_hs_lo[i] = __float2bfloat16(0.0f);
}
__global__ void conv_weights_kernel(const float* __restrict__ Wd,
                                    const float* __restrict__ Whh,
                                    const float* __restrict__ Ud) {
    int i = blockIdx.x * 256 + threadIdx.x;
    if (i < Mn * 2 * Pn) split_store(Wd[i], &g_Wd_hi[i], &g_Wd_lo[i]);
    if (i < G4n * Pn)    split_store(Whh[i], &g_Whh_hi[i], &g_Whh_lo[i]);
    if (i < Mn * Mn)     split_store(Ud[i],  &g_Ud_hi[i],  &g_Ud_lo[i]);
}
__global__ void conv_enc_kernel(const float* __restrict__ enc) {
    size_t i = ((size_t)blockIdx.x * 256 + threadIdx.x) * 4;
    float4 v = *(const float4*)&enc[i];
    __nv_bfloat16 h[4], l[4];
    float vv[4] = {v.x, v.y, v.z, v.w};
    #pragma unroll
    for (int q = 0; q < 4; q++) {
        h[q] = __float2bfloat16(vv[q]);
        l[q] = __float2bfloat16(vv[q] - __bfloat162float(h[q]));
    }
    __nv_bfloat162 ph0, ph1, pl0, pl1;
    ph0.x = h[0]; ph0.y = h[1]; ph1.x = h[2]; ph1.y = h[3];
    pl0.x = l[0]; pl0.y = l[1]; pl1.x = l[2]; pl1.y = l[3];
    *(__nv_bfloat162*)&g_enc_hi[i]     = ph0;
    *(__nv_bfloat162*)&g_enc_hi[i + 2] = ph1;
    *(__nv_bfloat162*)&g_enc_lo[i]     = pl0;
    *(__nv_bfloat162*)&g_enc_lo[i + 2] = pl1;
}

// ---------------- fold head (parallel): u = vy_w @ Wy_w ----------------------
// 16 CTAs x 256 thr; warp per output column j (8 j per CTA... 8 warps->8 j)
__global__ void __launch_bounds__(256) compute_u_kernel(
        const float* __restrict__ vy_w, const float* __restrict__ Wy_w,
        const float* __restrict__ Wy_b, const float* __restrict__ vy_b) {
    const int w = threadIdx.x >> 5, l = threadIdx.x & 31;
    const int j = blockIdx.x * 8 + w;           // 64 CTAs -> 512 outputs
    float s = 0.0f;
    #pragma unroll
    for (int n = l; n < Pn; n += 32) s += vy_w[n] * Wy_w[n * 512 + j];
    #pragma unroll
    for (int o = 16; o > 0; o >>= 1) s += __shfl_xor_sync(0xffffffffu, s, o);
    if (l == 0) g_u[j] = s;

    if (blockIdx.x == 0 && w == 0) {            // constant term
        float v = 0.0f;
        #pragma unroll
        for (int n = l; n < Pn; n += 32) v += vy_w[n] * Wy_b[n];
        #pragma unroll
        for (int o = 16; o > 0; o >>= 1) v += __shfl_xor_sync(0xffffffffu, v, o);
        if (l == 0) g_u[2 * Pn] = v + vy_b[0];
    }
}

// ---------------- split-bf16 MMA 64x64 tile, cp.async double-buffered -------
#define ST    40
#define PLB   (64 * ST * 2)          // bytes per plane  (5120)
#define BUFB  (4 * PLB)              // bytes per buffer (20480)

__device__ __forceinline__ void mma_tile64(
    const __nv_bfloat16* __restrict__ Ah, const __nv_bfloat16* __restrict__ Al,
    int lda,
    const __nv_bfloat16* __restrict__ Bh, const __nv_bfloat16* __restrict__ Bl,
    int ldb,
    float* __restrict__ C, int ldc, int r0, int c0, int k0, int K,
    const float* __restrict__ b1, const float* __restrict__ b2)
{
    __shared__ __align__(16) __nv_bfloat16 sm[2 * 4 * 64 * ST];
    const int tid = threadIdx.x;
    const int wid = tid >> 5, lane = tid & 31;
    const int wr = wid & 3, wc = wid >> 2;
    const uint32_t sb = (uint32_t)__cvta_generic_to_shared(sm);

    const int row = tid >> 2, ko = (tid & 3) * 8;
    const __nv_bfloat16* pAh = Ah + (size_t)(r0 + row) * lda + k0 + ko;
    const __nv_bfloat16* pAl = Al + (size_t)(r0 + row) * lda + k0 + ko;
    const __nv_bfloat16* pBh = Bh + (size_t)(c0 + row) * ldb + k0 + ko;
    const __nv_bfloat16* pBl = Bl + (size_t)(c0 + row) * ldb + k0 + ko;
    const uint32_t dA = sb + (uint32_t)(row * ST + ko) * 2;

    float acc[4][4];
    #pragma unroll
    for (int n = 0; n < 4; n++)
        #pragma unroll
        for (int i = 0; i < 4; i++) acc[n][i] = 0.0f;

    const int grp = lane >> 3, lr = lane & 7;
    const uint32_t aAddr = sb +
        (uint32_t)((wr * 16 + ((grp & 1) << 3) + lr) * ST + ((grp >> 1) << 3)) * 2;
    const uint32_t bAddr = sb + 2 * PLB +
        (uint32_t)((wc * 32 + ((grp >> 1) << 3) + lr) * ST + ((grp & 1) << 3)) * 2;

    const int nch = K >> 5;
    {
        cpa16(dA,            pAh);
        cpa16(dA + PLB,      pAl);
        cpa16(dA + 2 * PLB,  pBh);
        cpa16(dA + 3 * PLB,  pBl);
        cpa_commit();
    }
    for (int c = 0; c < nch; c++) {
        if (c + 1 < nch) {
            const int kb = (c + 1) * 32;
            const uint32_t d = dA + ((c + 1) & 1) * BUFB;
            cpa16(d,           pAh + kb);
            cpa16(d + PLB,     pAl + kb);
            cpa16(d + 2 * PLB, pBh + kb);
            cpa16(d + 3 * PLB, pBl + kb);
            cpa_commit();
            asm volatile("cp.async.wait_group 1;\n");
        } else {
            asm volatile("cp.async.wait_group 0;\n");
        }
        __syncthreads();
        const uint32_t bo = (c & 1) * BUFB;
        #pragma unroll
        for (int kk = 0; kk < 32; kk += 16) {
            uint32_t ah[4], al[4], bh[2][4], bl[2][4];
            ldm4(ah,   aAddr + bo + kk * 2);
            ldm4(al,   aAddr + bo + PLB + kk * 2);
            ldm4(bh[0], bAddr + bo + kk * 2);
            ldm4(bh[1], bAddr + bo + 16 * ST * 2 + kk * 2);
            ldm4(bl[0], bAddr + bo + PLB + kk * 2);
            ldm4(bl[1], bAddr + bo + PLB + 16 * ST * 2 + kk * 2);
            #pragma unroll
            for (int nt = 0; nt < 4; nt++) {
                const int p = nt >> 1, q = (nt & 1) * 2;
                mma_bf16(acc[nt], ah, bh[p][q], bh[p][q + 1]);   // hi*hi
                mma_bf16(acc[nt], ah, bl[p][q], bl[p][q + 1]);   // hi*lo
                mma_bf16(acc[nt], al, bh[p][q], bh[p][q + 1]);   // lo*hi
            }
        }
        __syncthreads();
    }

    const int rl = lane >> 2, cl = (lane & 3) * 2;
    const int gr = r0 + wr * 16 + rl;
    #pragma unroll
    for (int nt = 0; nt < 4; nt++) {
        const int gc = c0 + wc * 32 + nt * 8 + cl;
        float v0 = 0.0f, v1 = 0.0f;
        if (b1) { v0 += b1[gc]; v1 += b1[gc + 1]; }
        if (b2) { v0 += b2[gc]; v1 += b2[gc + 1]; }
        C[(size_t)gr * ldc + gc]           = acc[nt][0] + v0;
        C[(size_t)gr * ldc + gc + 1]       = acc[nt][1] + v1;
        C[(size_t)(gr + 8) * ldc + gc]     = acc[nt][2] + v0;
        C[(size_t)(gr + 8) * ldc + gc + 1] = acc[nt][3] + v1;
    }
}

// y1 = enc(32768x256) @ Ud^T(256x256)
__global__ void __launch_bounds__(256) y1_mma_kernel() {
    mma_tile64(g_enc_hi, g_enc_lo, Mn, g_Ud_hi, g_Ud_lo, Mn,
               g_y1, Mn, blockIdx.x * 64, blockIdx.y * 64, 0, Mn,
               nullptr, nullptr);
}

// per-step GEMMs, split-K x2:
//  full mode (ghonly=0): blockIdx.y in [0,40): y<8 -> x1 (4 col x 2 kh),
//                        y>=8 -> gh (16 col x 2 kh)
//  ghonly=1: blockIdx.y in [0,32) -> gh only
__global__ void __launch_bounds__(256) step_gemm_mma(
        const float* __restrict__ Wd_b, const float* __restrict__ bih,
        const float* __restrict__ bhh, int ghonly) {
    const int r0 = blockIdx.x * 64;
    int yy = blockIdx.y;
    if (!ghonly && yy < 8) {
        const int kh = yy & 1, ct = yy >> 1;
        mma_tile64(g_hs_hi, g_hs_lo, 512, g_Wd_hi, g_Wd_lo, 512,
                   kh ? g_x1p1 : g_x1p0, Mn, r0, ct * 64, kh * 256, 256,
                   kh ? nullptr : Wd_b, nullptr);
    } else {
        if (!ghonly) yy -= 8;
        const int kh = yy & 1, ct = yy >> 1;
        mma_tile64(g_hs_hi, g_hs_lo, 512, g_Whh_hi, g_Whh_lo, 256,
                   kh ? g_ghp1 : g_ghp0, G4n, r0, ct * 64, kh * 128, 128,
                   kh ? nullptr : bih, kh ? nullptr : bhh);
    }
}

// ---------------- fused attention + LSTM step (one CTA per batch row) -------
__global__ void __launch_bounds__(256) attn_step_kernel(
        const float* __restrict__ enc, const float* __restrict__ y,
        const float* __restrict__ vd_w, const float* __restrict__ wt_w,
        const float* __restrict__ wt_b, const float* __restrict__ Wih,
        int t_step) {
    const int b = blockIdx.x;
    const int tid = threadIdx.x;          // 256 threads, 8 warps
    const int w = tid >> 5, l = tid & 31;

    __shared__ float x1s[Mn];
    __shared__ float vs[Mn];
    __shared__ float ls[Tn];
    __shared__ float red8[8];
    __shared__ float s_ytil;

    x1s[tid] = g_x1p0[b * Mn + tid] + g_x1p1[b * Mn + tid];
    vs[tid]  = vd_w[tid];
    __syncthreads();

    // logits l[t] = sum_m tanh(x1[m] + y1[b,t,m]) * v[m]   (MUFU.TANH)
    #pragma unroll
    for (int idx = 0; idx < 8; idx++) {
        int t = w * 8 + idx;
        const float* y1row = &g_y1[((size_t)b * Tn + t) * Mn];
        float sum = 0.0f;
        #pragma unroll
        for (int j = 0; j < 8; j++) {
            int m = l + 32 * j;
            sum += tanh_fast(x1s[m] + y1row[m]) * vs[m];
        }
        #pragma unroll
        for (int o = 16; o > 0; o >>= 1) sum += __shfl_xor_sync(0xffffffffu, sum, o);
        if (l == 0) ls[t] = sum;
    }
    __syncthreads();

    if (w == 0) {                          // softmax over T=64
        float a = ls[l], c = ls[l + 32];
        float mx = fmaxf(a, c);
        #pragma unroll
        for (int o = 16; o > 0; o >>= 1) mx = fmaxf(mx, __shfl_xor_sync(0xffffffffu, mx, o));
        float e0 = __expf(a - mx), e1 = __expf(c - mx);
        float ts = e0 + e1;
        #pragma unroll
        for (int o = 16; o > 0; o >>= 1) ts += __shfl_xor_sync(0xffffffffu, ts, o);
        float inv = __fdividef(1.0f, ts);
        ls[l]      = e0 * inv;
        ls[l + 32] = e1 * inv;
    }
    __syncthreads();

    // context
    const int m = tid;
    float acc = 0.0f;
    const float* encb = &enc[(size_t)b * Tn * Mn];
    #pragma unroll 8
    for (int t = 0; t < Tn; t++) acc += ls[t] * encb[t * Mn + m];
    g_ct[b * Mn + m] = acc;

    float tot = block_reduce_256(acc * wt_w[m], red8);
    if (tid == 0)
        s_ytil = tot + y[b * Tn + t_step] * wt_w[Mn] + wt_b[0];
    __syncthreads();
    const float ytil = s_ytil;

    // LSTM cell (i,f,g,o; biases folded into ghp0) — accurate activations
    const float* gh0 = &g_ghp0[(size_t)b * G4n];
    const float* gh1 = &g_ghp1[(size_t)b * G4n];
    float ig = gh0[tid]        + gh1[tid]        + ytil * Wih[tid];
    float fg = gh0[tid + Pn]   + gh1[tid + Pn]   + ytil * Wih[tid + Pn];
    float gg = gh0[tid + 2*Pn] + gh1[tid + 2*Pn] + ytil * Wih[tid + 2*Pn];
    float og = gh0[tid + 3*Pn] + gh1[tid + 3*Pn] + ytil * Wih[tid + 3*Pn];
    float so = g_hs[b * 512 + 256 + tid];
    float cn = sigm(fg) * so + sigm(ig) * tanh_acc(gg);
    float hn = sigm(og) * tanh_acc(cn);
    g_hs[b * 512 + 256 + tid] = cn;
    g_hs[b * 512 + tid]       = hn;
    split_store(hn, &g_hs_hi[b * 512 + tid],       &g_hs_lo[b * 512 + tid]);
    split_store(cn, &g_hs_hi[b * 512 + 256 + tid], &g_hs_lo[b * 512 + 256 + tid]);
}

// ---------------- y_Tp1 head (warp per batch row) ---------------------------
__global__ void __launch_bounds__(256) head1_kernel(float* __restrict__ out) {
    int w = threadIdx.x >> 5, l = threadIdx.x & 31;
    int b = blockIdx.x * 8 + w;
    float sum = 0.0f;
    #pragma unroll
    for (int j = l; j < Pn; j += 32)
        sum += g_hs[b * 512 + j] * g_u[j] + g_ct[b * Mn + j] * g_u[Pn + j];
    #pragma unroll
    for (int o = 16; o > 0; o >>= 1) sum += __shfl_xor_sync(0xffffffffu, sum, o);
    if (l == 0) out[b] = sum + g_u[2 * Pn];
}

// ---------------- extra step e (0 or 1): y_til, LSTM, head ------------------
__global__ void __launch_bounds__(256) extra_step_kernel(
        const float* __restrict__ tar, const int* __restrict__ trainp,
        const float* __restrict__ wt_w, const float* __restrict__ wt_b,
        const float* __restrict__ Wih, float* __restrict__ out, int e) {
    const int b = blockIdx.x, tid = threadIdx.x;
    __shared__ float red8[8];
    __shared__ float s_ytil;

    const float ct = g_ct[b * Mn + tid];
    float dct = block_reduce_256(ct * wt_w[tid], red8);
    if (tid == 0) {
        int train = (trainp[0] != 0);
        float inp = train ? tar[b * 2 + e] : out[e * Bn + b];
        s_ytil = dct + inp * wt_w[Mn] + wt_b[0];
    }
    __syncthreads();
    const float ytil = s_ytil;

    const float* gh0 = &g_ghp0[(size_t)b * G4n];
    const float* gh1 = &g_ghp1[(size_t)b * G4n];
    float ig = gh0[tid]        + gh1[tid]        + ytil * Wih[tid];
    float fg = gh0[tid + Pn]   + gh1[tid + Pn]   + ytil * Wih[tid + Pn];
    float gg = gh0[tid + 2*Pn] + gh1[tid + 2*Pn] + ytil * Wih[tid + 2*Pn];
    float og = gh0[tid + 3*Pn] + gh1[tid + 3*Pn] + ytil * Wih[tid + 3*Pn];
    float so = g_hs[b * 512 + 256 + tid];
    float cn = sigm(fg) * so + sigm(ig) * tanh_acc(gg);
    float hn = sigm(og) * tanh_acc(cn);
    g_hs[b * 512 + 256 + tid] = cn;
    g_hs[b * 512 + tid]       = hn;
    split_store(hn, &g_hs_hi[b * 512 + tid],       &g_hs_lo[b * 512 + tid]);
    split_store(cn, &g_hs_hi[b * 512 + 256 + tid], &g_hs_lo[b * 512 + 256 + tid]);

    float tot = block_reduce_256(hn * g_u[tid] + ct * g_u[Pn + tid], red8);
    if (tid == 0) out[(e + 1) * Bn + b] = tot + g_u[2 * Pn];
}

// ---------------- launcher --------------------------------------------------
extern "C" void kernel_launch(void* const* d_in, const int* in_sizes, int n_in,
                              void* d_out, int out_size) {
    const float* enc   = (const float*)d_in[0];
    const float* y     = (const float*)d_in[1];
    const float* tar   = (const float*)d_in[2];
    const int*   train = (const int*)  d_in[3];
    const float* Wd_w  = (const float*)d_in[4];
    const float* Wd_b  = (const float*)d_in[5];
    const float* Ud_w  = (const float*)d_in[6];
    const float* vd_w  = (const float*)d_in[7];
    const float* wt_w  = (const float*)d_in[8];
    const float* wt_b  = (const float*)d_in[9];
    const float* Wy_w  = (const float*)d_in[10];
    const float* Wy_b  = (const float*)d_in[11];
    const float* vy_w  = (const float*)d_in[12];
    const float* vy_b  = (const float*)d_in[13];
    const float* Wih   = (const float*)d_in[14];
    const float* Whh   = (const float*)d_in[15];
    const float* bih   = (const float*)d_in[16];
    const float* bhh   = (const float*)d_in[17];
    float* out = (float*)d_out;

    init_state_kernel<<<Bn, 512>>>();
    conv_weights_kernel<<<1024, 256>>>(Wd_w, Whh, Ud_w);
    conv_enc_kernel<<<8192, 256>>>(enc);
    compute_u_kernel<<<64, 256>>>(vy_w, Wy_w, Wy_b, vy_b);
    y1_mma_kernel<<<dim3(512, 4), 256>>>();

    for (int t = 0; t < Tn; t++) {
        step_gemm_mma<<<dim3(8, 40), 256>>>(Wd_b, bih, bhh, 0);
        attn_step_kernel<<<Bn, 256>>>(enc, y, vd_w, wt_w, wt_b, Wih, t);
    }

    head1_kernel<<<Bn / 8, 256>>>(out);

    for (int e = 0; e < 2; e++) {
        step_gemm_mma<<<dim3(8, 32), 256>>>(Wd_b, bih, bhh, 1);
        extra_step_kernel<<<Bn, 256>>>(tar, train, wt_w, wt_b, Wih, out, e);
    }
}